// round 6
// baseline (speedup 1.0000x reference)
#include <cuda_runtime.h>
#include <math.h>

#define BB   256   // batch
#define TT   512   // timesteps
#define DD   64    // input dim
#define HH   512   // hidden
#define G4   2048  // 4*H
#define K0T  576   // D + H   (layer 0 concatenated K)
#define K1T  1024  // H + H   (layer 1 concatenated K)
#define NBLK 128   // persistent grid size (must all be co-resident; 128 <= 148 SMs)

// ---- device scratch (static: no allocation anywhere) ----
__device__ float g_W0[G4 * K0T];     // [2048 x 576]  = [w_ih_0 | w_hh_0]
__device__ float g_W1[G4 * K1T];     // [2048 x 1024] = [w_ih_1 | w_hh_1]
__device__ float g_b0[G4];
__device__ float g_b1[G4];
__device__ float g_h0[2][BB * HH];   // layer-0 h ping-pong (also layer-1 input)
__device__ float g_c0[BB * HH];
__device__ float g_h1[2][BB * HH];
__device__ float g_c1[BB * HH];
__device__ unsigned g_count;         // cumulative grid-barrier counter

// ---------------------------------------------------------------------------
// Pack weights (concat w_ih|w_hh per gate row), pre-add biases, zero states
// and the barrier counter. Runs every kernel_launch call -> deterministic.
// ---------------------------------------------------------------------------
__global__ void pack_kernel(const float* __restrict__ w_ih_0, const float* __restrict__ w_hh_0,
                            const float* __restrict__ b_ih_0, const float* __restrict__ b_hh_0,
                            const float* __restrict__ w_ih_1, const float* __restrict__ w_hh_1,
                            const float* __restrict__ b_ih_1, const float* __restrict__ b_hh_1)
{
    const int stride = gridDim.x * blockDim.x;
    const int idx = blockIdx.x * blockDim.x + threadIdx.x;

    if (idx == 0) g_count = 0u;

    for (int i = idx; i < G4 * K0T; i += stride) {
        int g = i / K0T, k = i % K0T;
        g_W0[i] = (k < DD) ? w_ih_0[g * DD + k] : w_hh_0[g * HH + (k - DD)];
    }
    for (int i = idx; i < G4 * K1T; i += stride) {
        int g = i / K1T, k = i % K1T;
        g_W1[i] = (k < HH) ? w_ih_1[g * HH + k] : w_hh_1[g * HH + (k - HH)];
    }
    for (int i = idx; i < G4; i += stride) {
        g_b0[i] = b_ih_0[i] + b_hh_0[i];
        g_b1[i] = b_ih_1[i] + b_hh_1[i];
    }
    for (int i = idx; i < BB * HH; i += stride) {
        g_h0[0][i] = 0.f; g_c0[i] = 0.f;
        g_h1[0][i] = 0.f; g_c1[i] = 0.f;
    }
}

__device__ __forceinline__ float sigmoidf_(float x) { return 1.0f / (1.0f + expf(-x)); }

// ---------------------------------------------------------------------------
// Grid barrier: cumulative counter, fence-based synchronization.
// Every block must pass every barrier; all NBLK blocks are co-resident.
// ---------------------------------------------------------------------------
__device__ __forceinline__ void grid_barrier(unsigned& target)
{
    __syncthreads();
    if (threadIdx.x == 0) {
        __threadfence();                 // release prior writes
        target += NBLK;
        atomicAdd(&g_count, 1u);
        while (*((volatile unsigned*)&g_count) < target) { }
        __threadfence();                 // acquire others' writes
    }
    __syncthreads();
}

// ---------------------------------------------------------------------------
// One 64(batch) x 64(gatecol) tile of one LSTM timestep, fused epilogue.
// Tile cols = 16 hidden units x 4 gates interleaved as j = 4*ul + gi
//   -> gate row g = gi*512 + u0 + ul. Thread owns 4 batch rows x one unit.
// ---------------------------------------------------------------------------
__device__ __forceinline__ void lstm_tile(
    const float* __restrict__ inA, int ldA, int K1, int KTOT,
    const float* __restrict__ hprev, const float* __restrict__ W,
    const float* __restrict__ bias, float* __restrict__ cst, float* __restrict__ hout,
    int b0, int u0, float (*As)[68], float (*Bs)[68])
{
    const int tid = threadIdx.x;       // 0..255
    const int tx  = tid & 15;          // unit within tile
    const int ty  = tid >> 4;          // batch group

    const int lj  = tid >> 2;          // 0..63 : tile row (A: batch) / tile col (B: gatecol)
    const int lk  = (tid & 3) << 2;    // 0,4,8,12 : k offset within BK=16
    const int gj  = ((lj & 3) << 9) + u0 + (lj >> 2);   // gate row for B load

    float acc[4][4];
    #pragma unroll
    for (int m = 0; m < 4; m++)
        #pragma unroll
        for (int g = 0; g < 4; g++) acc[m][g] = 0.f;

    for (int k0 = 0; k0 < KTOT; k0 += 16) {
        // ---- load A tile (batch x 16k), source switches at K1 (both multiples of 16)
        const float* arow; int ka;
        if (k0 < K1) { arow = inA   + (size_t)(b0 + lj) * ldA; ka = k0 + lk; }
        else         { arow = hprev + (size_t)(b0 + lj) * HH;  ka = k0 - K1 + lk; }
        float4 av = *reinterpret_cast<const float4*>(arow + ka);
        As[lk + 0][lj] = av.x;  As[lk + 1][lj] = av.y;
        As[lk + 2][lj] = av.z;  As[lk + 3][lj] = av.w;

        // ---- load B tile (64 gate rows x 16k)
        float4 bv = *reinterpret_cast<const float4*>(W + (size_t)gj * KTOT + k0 + lk);
        Bs[lk + 0][lj] = bv.x;  Bs[lk + 1][lj] = bv.y;
        Bs[lk + 2][lj] = bv.z;  Bs[lk + 3][lj] = bv.w;

        __syncthreads();

        #pragma unroll
        for (int kk = 0; kk < 16; kk++) {
            float4 a4 = *reinterpret_cast<const float4*>(&As[kk][ty << 2]);
            float4 b4 = *reinterpret_cast<const float4*>(&Bs[kk][tx << 2]);
            float a[4] = {a4.x, a4.y, a4.z, a4.w};
            float b[4] = {b4.x, b4.y, b4.z, b4.w};
            #pragma unroll
            for (int m = 0; m < 4; m++)
                #pragma unroll
                for (int g = 0; g < 4; g++)
                    acc[m][g] += a[m] * b[g];
        }
        __syncthreads();
    }

    // ---- fused LSTM epilogue: this thread = unit (u0+tx), batch rows b0+4*ty..+3
    const int u = u0 + tx;
    const float bi = bias[u];
    const float bf = bias[HH + u];
    const float bg = bias[2 * HH + u];
    const float bo = bias[3 * HH + u];

    #pragma unroll
    for (int m = 0; m < 4; m++) {
        const int b   = b0 + (ty << 2) + m;
        const int idx = b * HH + u;
        float ig = sigmoidf_(acc[m][0] + bi);
        float fg = sigmoidf_(acc[m][1] + bf);
        float gg = tanhf    (acc[m][2] + bg);
        float og = sigmoidf_(acc[m][3] + bo);
        float c  = fg * cst[idx] + ig * gg;
        cst[idx]  = c;
        hout[idx] = og * tanhf(c);
    }
}

// ---------------------------------------------------------------------------
// Persistent kernel: entire 512-step, 2-layer recurrence in ONE launch.
// Phase structure (independent work fused to halve barrier count):
//   phase -1 : layer0(t=0)                      | barrier
//   phase t  : layer1(t) ; layer0(t+1)          | barrier   (t = 0..510)
//   final    : layer1(511)
// ---------------------------------------------------------------------------
__global__ __launch_bounds__(256, 2)
void lstm_persistent(const float* __restrict__ x)
{
    __shared__ float As[16][68];
    __shared__ float Bs[16][68];

    const int b0 = blockIdx.y * 64;   // batch base   (gridDim.y = 4)
    const int u0 = blockIdx.x * 16;   // unit base    (gridDim.x = 32)
    unsigned target = 0;

    // layer0, t = 0
    lstm_tile(x, TT * DD, DD, K0T, g_h0[0], g_W0, g_b0, g_c0, g_h0[1],
              b0, u0, As, Bs);
    grid_barrier(target);

    for (int t = 0; t < TT - 1; t++) {
        const int p  = t & 1;
        // layer1(t): reads g_h0[p^1] (layer0 output at t) + g_h1[p]
        lstm_tile(g_h0[p ^ 1], HH, HH, K1T, g_h1[p], g_W1, g_b1, g_c1, g_h1[p ^ 1],
                  b0, u0, As, Bs);
        // layer0(t+1): reads x(t+1) + g_h0[p^1]; writes g_h0[p] (dead buffer)
        lstm_tile(x + (size_t)(t + 1) * DD, TT * DD, DD, K0T,
                  g_h0[p ^ 1], g_W0, g_b0, g_c0, g_h0[p],
                  b0, u0, As, Bs);
        grid_barrier(target);
    }

    // layer1, t = 511: p = 1, writes g_h1[0]
    lstm_tile(g_h0[0], HH, HH, K1T, g_h1[1], g_W1, g_b1, g_c1, g_h1[0],
              b0, u0, As, Bs);
}

// ---------------------------------------------------------------------------
// Final FC on last timestep: out[b] = h1_final[b,:] . fc_w + fc_b
// (layer1 at t=511 wrote g_h1[0])
// ---------------------------------------------------------------------------
__global__ void fc_kernel(const float* __restrict__ fc_w, const float* __restrict__ fc_b,
                          float* __restrict__ out)
{
    const int b = blockIdx.x;
    const float* h = g_h1[0] + (size_t)b * HH;
    float s = 0.f;
    for (int k = threadIdx.x; k < HH; k += 128) s += h[k] * fc_w[k];

    #pragma unroll
    for (int off = 16; off > 0; off >>= 1) s += __shfl_xor_sync(0xffffffffu, s, off);

    __shared__ float ws[4];
    if ((threadIdx.x & 31) == 0) ws[threadIdx.x >> 5] = s;
    __syncthreads();
    if (threadIdx.x == 0)
        out[b] = ws[0] + ws[1] + ws[2] + ws[3] + fc_b[0];
}

// ---------------------------------------------------------------------------
extern "C" void kernel_launch(void* const* d_in, const int* in_sizes, int n_in,
                              void* d_out, int out_size)
{
    const float* x      = (const float*)d_in[0];
    const float* w_ih_0 = (const float*)d_in[1];
    const float* w_hh_0 = (const float*)d_in[2];
    const float* b_ih_0 = (const float*)d_in[3];
    const float* b_hh_0 = (const float*)d_in[4];
    const float* w_ih_1 = (const float*)d_in[5];
    const float* w_hh_1 = (const float*)d_in[6];
    const float* b_ih_1 = (const float*)d_in[7];
    const float* b_hh_1 = (const float*)d_in[8];
    const float* fc_w   = (const float*)d_in[9];
    const float* fc_b   = (const float*)d_in[10];
    float* out = (float*)d_out;

    pack_kernel<<<512, 256>>>(w_ih_0, w_hh_0, b_ih_0, b_hh_0,
                              w_ih_1, w_hh_1, b_ih_1, b_hh_1);

    dim3 grid(HH / 16, BB / 64);   // 32 x 4 = 128 persistent blocks
    lstm_persistent<<<grid, 256>>>(x);

    fc_kernel<<<BB, 128>>>(fc_w, fc_b, out);
}

// round 8
// speedup vs baseline: 3.7426x; 3.7426x over previous
#include <cuda_runtime.h>
#include <cuda_bf16.h>
#include <math.h>
#include <stdint.h>

#define BB 256
#define TT 512
#define HH 512
#define G4 2048

// ---- device images (static; no allocation anywhere) ----
// A-fragment image block per ki (16 k): [hi: 8 mi x 32 lane x 16B = 4KB][lo: 4KB] = 8KB
// W-fragment image block per ki:        [hi: 4 p x 32 lane x 16B = 2KB][lo: 2KB] = 4KB
__device__ uint4 g_ximg [(size_t)TT * 2 * 2048];     // [t][half] : 4 ki * 8KB = 32KB
__device__ uint4 g_W1img[(size_t)32 * 16384];        // [gt] : 64 ki * 4KB = 256KB
__device__ uint4 g_W0img[(size_t)32 * 9216];         // [gt] : 36 ki * 4KB = 144KB
__device__ uint4 g_h0img[(size_t)2 * 2 * 16384];     // [slot][half] : 32 ki * 8KB = 256KB
__device__ uint4 g_h1img[(size_t)2 * 2 * 16384];
__device__ float g_b0[G4], g_b1[G4];
__device__ float g_h1last[BB * HH];
__device__ unsigned g_cnt[2];

__device__ __forceinline__ float sg(float x) { return 1.0f / (1.0f + expf(-x)); }

__device__ __forceinline__ void bsplit2(float f0, float f1, unsigned& hi, unsigned& lo) {
    __nv_bfloat16 h0 = __float2bfloat16(f0), h1 = __float2bfloat16(f1);
    float r0 = f0 - __bfloat162float(h0), r1 = f1 - __bfloat162float(h1);
    __nv_bfloat16 l0 = __float2bfloat16(r0), l1 = __float2bfloat16(r1);
    hi = (unsigned)__bfloat16_as_ushort(h0) | ((unsigned)__bfloat16_as_ushort(h1) << 16);
    lo = (unsigned)__bfloat16_as_ushort(l0) | ((unsigned)__bfloat16_as_ushort(l1) << 16);
}

#define MMA(c, a, bx, by) \
    asm volatile("mma.sync.aligned.m16n8k16.row.col.f32.bf16.bf16.f32 " \
        "{%0,%1,%2,%3}, {%4,%5,%6,%7}, {%8,%9}, {%0,%1,%2,%3};" \
        : "+f"((c)[0]), "+f"((c)[1]), "+f"((c)[2]), "+f"((c)[3]) \
        : "r"((a).x), "r"((a).y), "r"((a).z), "r"((a).w), "r"(bx), "r"(by))

// =================== pack: build fragment-exact images ===================
__global__ void pack_kernel(const float* __restrict__ x,
    const float* __restrict__ wi0, const float* __restrict__ wh0,
    const float* __restrict__ bi0, const float* __restrict__ bh0,
    const float* __restrict__ wi1, const float* __restrict__ wh1,
    const float* __restrict__ bi1, const float* __restrict__ bh1)
{
    const long long stride = (long long)gridDim.x * blockDim.x;
    const long long t0 = (long long)blockIdx.x * blockDim.x + threadIdx.x;
    if (t0 == 0) { g_cnt[0] = 0u; g_cnt[1] = 0u; }
    for (long long i = t0; i < G4; i += stride) { g_b0[i] = bi0[i] + bh0[i]; g_b1[i] = bi1[i] + bh1[i]; }
    uint4 z = make_uint4(0, 0, 0, 0);
    for (long long i = t0; i < 2 * 2 * 16384; i += stride) { g_h0img[i] = z; g_h1img[i] = z; }

    // ---- x image: i = (((t*2+half)*4+ki)*8+mi)*32+lane
    for (long long i = t0; i < (long long)TT * 2 * 4 * 8 * 32; i += stride) {
        int lane = (int)(i & 31), mi = (int)((i >> 5) & 7), ki = (int)((i >> 8) & 3);
        int half = (int)((i >> 10) & 1), t = (int)(i >> 11);
        int r0 = mi * 16 + (lane >> 2), k0 = ki * 16 + (lane & 3) * 2;
        const float* xb = x + ((size_t)(half * 128 + r0) * TT + t) * 64;
        const float* xb8 = xb + (size_t)8 * TT * 64;
        uint4 hi, lo;
        bsplit2(xb [k0],     xb [k0 + 1],     hi.x, lo.x);   // R0: (r0,   k0..k0+1)
        bsplit2(xb8[k0],     xb8[k0 + 1],     hi.y, lo.y);   // R1: (r0+8, k0..k0+1)
        bsplit2(xb [k0 + 8], xb [k0 + 9],     hi.z, lo.z);   // R2: (r0,   k0+8..9)
        bsplit2(xb8[k0 + 8], xb8[k0 + 9],     hi.w, lo.w);   // R3: (r0+8, k0+8..9)
        char* dst = (char*)g_ximg + ((size_t)t * 2 + half) * 32768 + ki * 8192 + (mi * 32 + lane) * 16;
        *(uint4*)dst = hi; *(uint4*)(dst + 4096) = lo;
    }

    // ---- W1 image: i = ((gt*64+ki)*32+lane)*4+p ; cols j = ni*8 + lane/4, ni = 2p(+1)
    for (long long i = t0; i < (long long)32 * 64 * 32 * 4; i += stride) {
        int p = (int)(i & 3), lane = (int)((i >> 2) & 31), ki = (int)((i >> 7) & 63), gt = (int)(i >> 13);
        int j0 = p * 16 + (lane >> 2), j1 = j0 + 8;
        int k0 = ki * 16 + (lane & 3) * 2;
        int G0 = (j0 & 3) * 512 + gt * 16 + (j0 >> 2);
        int G1 = (j1 & 3) * 512 + gt * 16 + (j1 >> 2);
        const float* s00 = (k0 < 512)     ? wi1 + (size_t)G0 * 512 + k0     : wh1 + (size_t)G0 * 512 + k0 - 512;
        const float* s08 = (k0 + 8 < 512) ? wi1 + (size_t)G0 * 512 + k0 + 8 : wh1 + (size_t)G0 * 512 + k0 + 8 - 512;
        const float* s10 = (k0 < 512)     ? wi1 + (size_t)G1 * 512 + k0     : wh1 + (size_t)G1 * 512 + k0 - 512;
        const float* s18 = (k0 + 8 < 512) ? wi1 + (size_t)G1 * 512 + k0 + 8 : wh1 + (size_t)G1 * 512 + k0 + 8 - 512;
        uint4 hi, lo;
        bsplit2(s00[0], s00[1], hi.x, lo.x);
        bsplit2(s08[0], s08[1], hi.y, lo.y);
        bsplit2(s10[0], s10[1], hi.z, lo.z);
        bsplit2(s18[0], s18[1], hi.w, lo.w);
        char* dst = (char*)g_W1img + (size_t)gt * 262144 + ki * 4096 + (p * 32 + lane) * 16;
        *(uint4*)dst = hi; *(uint4*)(dst + 2048) = lo;
    }

    // ---- W0 image: K = 576 -> 36 ki ; k<64 from wi0 else wh0
    for (long long i = t0; i < (long long)32 * 36 * 32 * 4; i += stride) {
        int p = (int)(i & 3), lane = (int)((i >> 2) & 31);
        int rem = (int)(i >> 7); int ki = rem % 36, gt = rem / 36;
        int j0 = p * 16 + (lane >> 2), j1 = j0 + 8;
        int k0 = ki * 16 + (lane & 3) * 2;
        int G0 = (j0 & 3) * 512 + gt * 16 + (j0 >> 2);
        int G1 = (j1 & 3) * 512 + gt * 16 + (j1 >> 2);
        const float* s00 = (k0 < 64)     ? wi0 + (size_t)G0 * 64 + k0     : wh0 + (size_t)G0 * 512 + k0 - 64;
        const float* s08 = (k0 + 8 < 64) ? wi0 + (size_t)G0 * 64 + k0 + 8 : wh0 + (size_t)G0 * 512 + k0 + 8 - 64;
        const float* s10 = (k0 < 64)     ? wi0 + (size_t)G1 * 64 + k0     : wh0 + (size_t)G1 * 512 + k0 - 64;
        const float* s18 = (k0 + 8 < 64) ? wi0 + (size_t)G1 * 64 + k0 + 8 : wh0 + (size_t)G1 * 512 + k0 + 8 - 64;
        uint4 hi, lo;
        bsplit2(s00[0], s00[1], hi.x, lo.x);
        bsplit2(s08[0], s08[1], hi.y, lo.y);
        bsplit2(s10[0], s10[1], hi.z, lo.z);
        bsplit2(s18[0], s18[1], hi.w, lo.w);
        char* dst = (char*)g_W0img + (size_t)gt * 147456 + ki * 4096 + (p * 32 + lane) * 16;
        *(uint4*)dst = hi; *(uint4*)(dst + 2048) = lo;
    }
}

// =================== grid barrier (cumulative, 2 domains of 64 CTAs) ===================
__device__ __forceinline__ void gbar(int dom, unsigned& tgt)
{
    __syncthreads();
    if (threadIdx.x == 0) {
        __threadfence();
        tgt += 64;
        atomicAdd(&g_cnt[dom], 1u);
        while (*(volatile unsigned*)&g_cnt[dom] < tgt) { }
        __threadfence();
    }
    __syncthreads();
}

// =================== one layer-step for one CTA ===================
__device__ void stepH(const char* __restrict__ aA, int nA,
                      const char* __restrict__ aB, int nB,
                      const char* __restrict__ wI,
                      const float* __restrict__ bs, float* creg,
                      char* hImg, float* hlast, int gt, float (*Ds)[68])
{
    const int tid = threadIdx.x, lane = tid & 31, wz = tid >> 5;
    float acc[2][8][4];
    #pragma unroll
    for (int m = 0; m < 2; m++)
        #pragma unroll
        for (int n = 0; n < 8; n++)
            #pragma unroll
            for (int q = 0; q < 4; q++) acc[m][n][q] = 0.f;

    auto chunk = [&](const char* ab, const char* wb) {
        uint4 ah[2], al[2], wh[4], wl[4];
        #pragma unroll
        for (int m = 0; m < 2; m++) {
            const char* pa = ab + ((wz * 2 + m) * 32 + lane) * 16;
            ah[m] = *(const uint4*)pa; al[m] = *(const uint4*)(pa + 4096);
        }
        #pragma unroll
        for (int p = 0; p < 4; p++) {
            const char* pw = wb + (p * 32 + lane) * 16;
            wh[p] = *(const uint4*)pw; wl[p] = *(const uint4*)(pw + 2048);
        }
        #pragma unroll
        for (int m = 0; m < 2; m++)
            #pragma unroll
            for (int p = 0; p < 4; p++) {
                MMA(acc[m][2*p],   ah[m], wh[p].x, wh[p].y);
                MMA(acc[m][2*p+1], ah[m], wh[p].z, wh[p].w);
                MMA(acc[m][2*p],   ah[m], wl[p].x, wl[p].y);
                MMA(acc[m][2*p+1], ah[m], wl[p].z, wl[p].w);
                MMA(acc[m][2*p],   al[m], wh[p].x, wh[p].y);
                MMA(acc[m][2*p+1], al[m], wh[p].z, wh[p].w);
            }
    };

    int c = 0;
    for (int ki = 0; ki < nA; ki++, c++) chunk(aA + (size_t)ki * 8192, wI + (size_t)c * 4096);
    for (int ki = 0; ki < nB; ki++, c++) chunk(aB + (size_t)ki * 8192, wI + (size_t)c * 4096);

    // ---- stage D to SMEM (row-major) ----
    #pragma unroll
    for (int m = 0; m < 2; m++)
        #pragma unroll
        for (int n = 0; n < 8; n++) {
            int r0 = wz * 32 + m * 16 + (lane >> 2), c0 = n * 8 + (lane & 3) * 2;
            Ds[r0][c0]     = acc[m][n][0];
            Ds[r0][c0 + 1] = acc[m][n][1];
            Ds[r0 + 8][c0]     = acc[m][n][2];
            Ds[r0 + 8][c0 + 1] = acc[m][n][3];
        }
    __syncthreads();

    // ---- gate math: thread owns row tid, 16 units ----
    const int r = tid;
    float h[16];
    #pragma unroll
    for (int ul = 0; ul < 16; ul++) {
        float gi = sg(Ds[r][4*ul + 0] + bs[4*ul + 0]);
        float gf = sg(Ds[r][4*ul + 1] + bs[4*ul + 1]);
        float gg = tanhf(Ds[r][4*ul + 2] + bs[4*ul + 2]);
        float go = sg(Ds[r][4*ul + 3] + bs[4*ul + 3]);
        float cc = gf * creg[ul] + gi * gg;
        creg[ul] = cc;
        h[ul] = go * tanhf(cc);
    }

    if (hImg) {   // write h as bf16 hi/lo A-fragments at ki = gt
        int rl = r & 15, mi = r >> 4;
        char* base = hImg + gt * 8192 + mi * 512;
        #pragma unroll
        for (int u2 = 0; u2 < 8; u2++) {
            unsigned hi32, lo32;
            bsplit2(h[2*u2], h[2*u2 + 1], hi32, lo32);
            int lane2 = (rl & 7) * 4 + (u2 & 3);
            int p4 = (rl >> 3) + 2 * (u2 >> 2);
            *(unsigned*)(base + lane2 * 16 + p4 * 4) = hi32;
            *(unsigned*)(base + 4096 + lane2 * 16 + p4 * 4) = lo32;
        }
    }
    if (hlast) {
        #pragma unroll
        for (int ul = 0; ul < 16; ul++) hlast[gt * 16 + ul] = h[ul];
    }
    __syncthreads();
}

// =================== persistent recurrence ===================
__global__ __launch_bounds__(128, 1) void lstm_persistent()
{
    __shared__ float Ds[128][68];
    __shared__ float bs[64];
    const int tid = threadIdx.x, cta = blockIdx.x;
    const int lyr  = cta >> 6;          // 0: layer1 worker, 1: layer0 worker
    const int half = (cta >> 5) & 1;
    const int gt   = cta & 31;

    const float* bias = lyr ? g_b0 : g_b1;
    if (tid < 64) bs[tid] = bias[(tid & 3) * 512 + gt * 16 + (tid >> 2)];
    __syncthreads();

    float creg[16];
    #pragma unroll
    for (int i = 0; i < 16; i++) creg[i] = 0.f;
    unsigned tgt = 0u;

    const char* w1 = (const char*)g_W1img + (size_t)gt * 262144;
    const char* w0 = (const char*)g_W0img + (size_t)gt * 147456;
    #define XI(t)  ((char*)g_ximg  + ((size_t)(t) * 2 + half) * 32768)
    #define H0I(s) ((char*)g_h0img + ((size_t)((s) * 2 + half)) * 262144)
    #define H1I(s) ((char*)g_h1img + ((size_t)((s) * 2 + half)) * 262144)

    // prologue: layer0(t=0) reads h0 slot1 (zeros), writes slot0
    if (lyr == 1)
        stepH(XI(0), 4, H0I(1), 32, w0, bs, creg, H0I(0), nullptr, gt, Ds);
    gbar(half, tgt);

    for (int p = 0; p < TT - 1; p++) {
        const int s = p & 1;
        if (lyr == 0)   // layer1(p): A = h0(slot s) || h1(slot s^1); writes h1 slot s
            stepH(H0I(s), 32, H1I(s ^ 1), 32, w1, bs, creg, H1I(s), nullptr, gt, Ds);
        else            // layer0(p+1): A = x(p+1) || h0(slot s); writes h0 slot s^1
            stepH(XI(p + 1), 4, H0I(s), 32, w0, bs, creg, H0I(s ^ 1), nullptr, gt, Ds);
        gbar(half, tgt);
    }

    // layer1(511): A = h0 slot1 || h1 slot0 ; fp32 output only
    if (lyr == 0)
        stepH(H0I(1), 32, H1I(0), 32, w1, bs, creg, nullptr,
              g_h1last + (size_t)(half * 128 + tid) * HH, gt, Ds);
}

// =================== final FC ===================
__global__ void fc_kernel(const float* __restrict__ fc_w, const float* __restrict__ fc_b,
                          float* __restrict__ out)
{
    const int b = blockIdx.x;
    const float* h = g_h1last + (size_t)b * HH;
    float s = 0.f;
    for (int k = threadIdx.x; k < HH; k += 128) s += h[k] * fc_w[k];
    #pragma unroll
    for (int off = 16; off > 0; off >>= 1) s += __shfl_xor_sync(0xffffffffu, s, off);
    __shared__ float ws[4];
    if ((threadIdx.x & 31) == 0) ws[threadIdx.x >> 5] = s;
    __syncthreads();
    if (threadIdx.x == 0) out[b] = ws[0] + ws[1] + ws[2] + ws[3] + fc_b[0];
}

extern "C" void kernel_launch(void* const* d_in, const int* in_sizes, int n_in,
                              void* d_out, int out_size)
{
    const float* x   = (const float*)d_in[0];
    const float* wi0 = (const float*)d_in[1];
    const float* wh0 = (const float*)d_in[2];
    const float* bi0 = (const float*)d_in[3];
    const float* bh0 = (const float*)d_in[4];
    const float* wi1 = (const float*)d_in[5];
    const float* wh1 = (const float*)d_in[6];
    const float* bi1 = (const float*)d_in[7];
    const float* bh1 = (const float*)d_in[8];
    const float* fcw = (const float*)d_in[9];
    const float* fcb = (const float*)d_in[10];
    float* out = (float*)d_out;

    pack_kernel<<<1024, 256>>>(x, wi0, wh0, bi0, bh0, wi1, wh1, bi1, bh1);
    lstm_persistent<<<128, 128>>>();
    fc_kernel<<<BB, 128>>>(fcw, fcb, out);
}

// round 9
// speedup vs baseline: 4.2509x; 1.1358x over previous
#include <cuda_runtime.h>
#include <cuda_bf16.h>
#include <math.h>
#include <stdint.h>

#define BB 256
#define TT 512
#define HH 512
#define G4 2048

// ---- device images (static; no allocation anywhere) ----
// A-fragment image block per ki (16 k): [hi: 8 mi x 32 lane x 16B = 4KB][lo: 4KB] = 8KB
// W-fragment image block per ki:        [hi: 4 p x 32 lane x 16B = 2KB][lo: 2KB] = 4KB
__device__ uint4 g_ximg [(size_t)TT * 2 * 2048];     // [t][half] : 4 ki * 8KB = 32KB
__device__ uint4 g_W1img[(size_t)32 * 16384];        // [gt] : 64 ki * 4KB = 256KB
__device__ uint4 g_W0img[(size_t)32 * 9216];         // [gt] : 36 ki * 4KB = 144KB
__device__ uint4 g_h0img[(size_t)2 * 2 * 16384];     // [slot][half] : 32 ki * 8KB = 256KB
__device__ uint4 g_h1img[(size_t)2 * 2 * 16384];
__device__ float g_b0[G4], g_b1[G4];
__device__ float g_h1last[BB * HH];
__device__ unsigned g_cnt[2];

// fast, saturation-safe gates (slack vs 1e-3 tol is ~200x)
__device__ __forceinline__ float sg(float x) { return __fdividef(1.0f, 1.0f + __expf(-x)); }
__device__ __forceinline__ float th(float x) { return 1.0f - __fdividef(2.0f, __expf(2.0f * x) + 1.0f); }

__device__ __forceinline__ void bsplit2(float f0, float f1, unsigned& hi, unsigned& lo) {
    __nv_bfloat16 h0 = __float2bfloat16(f0), h1 = __float2bfloat16(f1);
    float r0 = f0 - __bfloat162float(h0), r1 = f1 - __bfloat162float(h1);
    __nv_bfloat16 l0 = __float2bfloat16(r0), l1 = __float2bfloat16(r1);
    hi = (unsigned)__bfloat16_as_ushort(h0) | ((unsigned)__bfloat16_as_ushort(h1) << 16);
    lo = (unsigned)__bfloat16_as_ushort(l0) | ((unsigned)__bfloat16_as_ushort(l1) << 16);
}

#define MMA(c, a, bx, by) \
    asm volatile("mma.sync.aligned.m16n8k16.row.col.f32.bf16.bf16.f32 " \
        "{%0,%1,%2,%3}, {%4,%5,%6,%7}, {%8,%9}, {%0,%1,%2,%3};" \
        : "+f"((c)[0]), "+f"((c)[1]), "+f"((c)[2]), "+f"((c)[3]) \
        : "r"((a).x), "r"((a).y), "r"((a).z), "r"((a).w), "r"(bx), "r"(by))

// =================== pack: build fragment-exact images ===================
__global__ void pack_kernel(const float* __restrict__ x,
    const float* __restrict__ wi0, const float* __restrict__ wh0,
    const float* __restrict__ bi0, const float* __restrict__ bh0,
    const float* __restrict__ wi1, const float* __restrict__ wh1,
    const float* __restrict__ bi1, const float* __restrict__ bh1)
{
    const long long stride = (long long)gridDim.x * blockDim.x;
    const long long t0 = (long long)blockIdx.x * blockDim.x + threadIdx.x;
    if (t0 == 0) { g_cnt[0] = 0u; g_cnt[1] = 0u; }
    for (long long i = t0; i < G4; i += stride) { g_b0[i] = bi0[i] + bh0[i]; g_b1[i] = bi1[i] + bh1[i]; }
    uint4 z = make_uint4(0, 0, 0, 0);
    for (long long i = t0; i < 2 * 2 * 16384; i += stride) { g_h0img[i] = z; g_h1img[i] = z; }

    // ---- x image: i = (((t*2+half)*4+ki)*8+mi)*32+lane
    for (long long i = t0; i < (long long)TT * 2 * 4 * 8 * 32; i += stride) {
        int lane = (int)(i & 31), mi = (int)((i >> 5) & 7), ki = (int)((i >> 8) & 3);
        int half = (int)((i >> 10) & 1), t = (int)(i >> 11);
        int r0 = mi * 16 + (lane >> 2), k0 = ki * 16 + (lane & 3) * 2;
        const float* xb = x + ((size_t)(half * 128 + r0) * TT + t) * 64;
        const float* xb8 = xb + (size_t)8 * TT * 64;
        uint4 hi, lo;
        bsplit2(xb [k0],     xb [k0 + 1],     hi.x, lo.x);
        bsplit2(xb8[k0],     xb8[k0 + 1],     hi.y, lo.y);
        bsplit2(xb [k0 + 8], xb [k0 + 9],     hi.z, lo.z);
        bsplit2(xb8[k0 + 8], xb8[k0 + 9],     hi.w, lo.w);
        char* dst = (char*)g_ximg + ((size_t)t * 2 + half) * 32768 + ki * 8192 + (mi * 32 + lane) * 16;
        *(uint4*)dst = hi; *(uint4*)(dst + 4096) = lo;
    }

    // ---- W1 image
    for (long long i = t0; i < (long long)32 * 64 * 32 * 4; i += stride) {
        int p = (int)(i & 3), lane = (int)((i >> 2) & 31), ki = (int)((i >> 7) & 63), gt = (int)(i >> 13);
        int j0 = p * 16 + (lane >> 2), j1 = j0 + 8;
        int k0 = ki * 16 + (lane & 3) * 2;
        int G0 = (j0 & 3) * 512 + gt * 16 + (j0 >> 2);
        int G1 = (j1 & 3) * 512 + gt * 16 + (j1 >> 2);
        const float* s00 = (k0 < 512)     ? wi1 + (size_t)G0 * 512 + k0     : wh1 + (size_t)G0 * 512 + k0 - 512;
        const float* s08 = (k0 + 8 < 512) ? wi1 + (size_t)G0 * 512 + k0 + 8 : wh1 + (size_t)G0 * 512 + k0 + 8 - 512;
        const float* s10 = (k0 < 512)     ? wi1 + (size_t)G1 * 512 + k0     : wh1 + (size_t)G1 * 512 + k0 - 512;
        const float* s18 = (k0 + 8 < 512) ? wi1 + (size_t)G1 * 512 + k0 + 8 : wh1 + (size_t)G1 * 512 + k0 + 8 - 512;
        uint4 hi, lo;
        bsplit2(s00[0], s00[1], hi.x, lo.x);
        bsplit2(s08[0], s08[1], hi.y, lo.y);
        bsplit2(s10[0], s10[1], hi.z, lo.z);
        bsplit2(s18[0], s18[1], hi.w, lo.w);
        char* dst = (char*)g_W1img + (size_t)gt * 262144 + ki * 4096 + (p * 32 + lane) * 16;
        *(uint4*)dst = hi; *(uint4*)(dst + 2048) = lo;
    }

    // ---- W0 image: K = 576 -> 36 ki ; k<64 from wi0 else wh0
    for (long long i = t0; i < (long long)32 * 36 * 32 * 4; i += stride) {
        int p = (int)(i & 3), lane = (int)((i >> 2) & 31);
        int rem = (int)(i >> 7); int ki = rem % 36, gt = rem / 36;
        int j0 = p * 16 + (lane >> 2), j1 = j0 + 8;
        int k0 = ki * 16 + (lane & 3) * 2;
        int G0 = (j0 & 3) * 512 + gt * 16 + (j0 >> 2);
        int G1 = (j1 & 3) * 512 + gt * 16 + (j1 >> 2);
        const float* s00 = (k0 < 64)     ? wi0 + (size_t)G0 * 64 + k0     : wh0 + (size_t)G0 * 512 + k0 - 64;
        const float* s08 = (k0 + 8 < 64) ? wi0 + (size_t)G0 * 64 + k0 + 8 : wh0 + (size_t)G0 * 512 + k0 + 8 - 64;
        const float* s10 = (k0 < 64)     ? wi0 + (size_t)G1 * 64 + k0     : wh0 + (size_t)G1 * 512 + k0 - 64;
        const float* s18 = (k0 + 8 < 64) ? wi0 + (size_t)G1 * 64 + k0 + 8 : wh0 + (size_t)G1 * 512 + k0 + 8 - 64;
        uint4 hi, lo;
        bsplit2(s00[0], s00[1], hi.x, lo.x);
        bsplit2(s08[0], s08[1], hi.y, lo.y);
        bsplit2(s10[0], s10[1], hi.z, lo.z);
        bsplit2(s18[0], s18[1], hi.w, lo.w);
        char* dst = (char*)g_W0img + (size_t)gt * 147456 + ki * 4096 + (p * 32 + lane) * 16;
        *(uint4*)dst = hi; *(uint4*)(dst + 2048) = lo;
    }
}

// =================== grid barrier (cumulative, 2 domains of 64 CTAs) ===================
__device__ __forceinline__ void gbar(int dom, unsigned& tgt)
{
    __syncthreads();
    if (threadIdx.x == 0) {
        __threadfence();
        tgt += 64;
        atomicAdd(&g_cnt[dom], 1u);
        while (*(volatile unsigned*)&g_cnt[dom] < tgt) { }
        __threadfence();
    }
    __syncthreads();
}

// =================== one layer-step for one CTA (software-pipelined) ===================
__device__ void stepH(const char* __restrict__ aA, int nA,
                      const char* __restrict__ aB, int nB,
                      const char* __restrict__ wI,
                      const float* __restrict__ bs, float* creg,
                      char* hImg, float* hlast, int gt, float (*Ds)[68])
{
    const int tid = threadIdx.x, lane = tid & 31, wz = tid >> 5;
    const int nCh = nA + nB;           // 36 or 64 : always even
    float acc[2][8][4];
    #pragma unroll
    for (int m = 0; m < 2; m++)
        #pragma unroll
        for (int n = 0; n < 8; n++)
            #pragma unroll
            for (int q = 0; q < 4; q++) acc[m][n][q] = 0.f;

    // two explicit register buffers (compile-time names -> no local mem)
    uint4 ahA[2], alA[2], whA[4], wlA[4];
    uint4 ahB[2], alB[2], whB[4], wlB[4];

#define LDCH(S, c) do { \
    const char* ab_ = ((c) < nA) ? aA + (size_t)(c) * 8192 : aB + (size_t)((c) - nA) * 8192; \
    const char* wb_ = wI + (size_t)(c) * 4096; \
    const char* pa0_ = ab_ + ((wz * 2) * 32 + lane) * 16; \
    const char* pa1_ = pa0_ + 512; \
    ah##S[0] = *(const uint4*)pa0_;  al##S[0] = *(const uint4*)(pa0_ + 4096); \
    ah##S[1] = *(const uint4*)pa1_;  al##S[1] = *(const uint4*)(pa1_ + 4096); \
    _Pragma("unroll") \
    for (int p_ = 0; p_ < 4; p_++) { \
        const char* pw_ = wb_ + (p_ * 32 + lane) * 16; \
        wh##S[p_] = *(const uint4*)pw_;  wl##S[p_] = *(const uint4*)(pw_ + 2048); \
    } \
} while (0)

// term-major ordering: 16 MMAs per pass, same-acc reuse distance = 16 >= HMMA latency
#define MMACH(S) do { \
    _Pragma("unroll") \
    for (int m_ = 0; m_ < 2; m_++) \
        _Pragma("unroll") \
        for (int p_ = 0; p_ < 4; p_++) { \
            MMA(acc[m_][2*p_],   ah##S[m_], wh##S[p_].x, wh##S[p_].y); \
            MMA(acc[m_][2*p_+1], ah##S[m_], wh##S[p_].z, wh##S[p_].w); \
        } \
    _Pragma("unroll") \
    for (int m_ = 0; m_ < 2; m_++) \
        _Pragma("unroll") \
        for (int p_ = 0; p_ < 4; p_++) { \
            MMA(acc[m_][2*p_],   ah##S[m_], wl##S[p_].x, wl##S[p_].y); \
            MMA(acc[m_][2*p_+1], ah##S[m_], wl##S[p_].z, wl##S[p_].w); \
        } \
    _Pragma("unroll") \
    for (int m_ = 0; m_ < 2; m_++) \
        _Pragma("unroll") \
        for (int p_ = 0; p_ < 4; p_++) { \
            MMA(acc[m_][2*p_],   al##S[m_], wh##S[p_].x, wh##S[p_].y); \
            MMA(acc[m_][2*p_+1], al##S[m_], wh##S[p_].z, wh##S[p_].w); \
        } \
} while (0)

    LDCH(A, 0);
    for (int c = 0; c < nCh; c += 2) {
        LDCH(B, c + 1);                    // nCh even -> c+1 always valid
        MMACH(A);
        if (c + 2 < nCh) LDCH(A, c + 2);
        MMACH(B);
    }
#undef LDCH
#undef MMACH

    // ---- stage D to SMEM (row-major) ----
    #pragma unroll
    for (int m = 0; m < 2; m++)
        #pragma unroll
        for (int n = 0; n < 8; n++) {
            int r0 = wz * 32 + m * 16 + (lane >> 2), c0 = n * 8 + (lane & 3) * 2;
            Ds[r0][c0]     = acc[m][n][0];
            Ds[r0][c0 + 1] = acc[m][n][1];
            Ds[r0 + 8][c0]     = acc[m][n][2];
            Ds[r0 + 8][c0 + 1] = acc[m][n][3];
        }
    __syncthreads();

    // ---- gate math: thread owns row tid, 16 units ----
    const int r = tid;
    float h[16];
    #pragma unroll
    for (int ul = 0; ul < 16; ul++) {
        float gi = sg(Ds[r][4*ul + 0] + bs[4*ul + 0]);
        float gf = sg(Ds[r][4*ul + 1] + bs[4*ul + 1]);
        float gg = th(Ds[r][4*ul + 2] + bs[4*ul + 2]);
        float go = sg(Ds[r][4*ul + 3] + bs[4*ul + 3]);
        float cc = gf * creg[ul] + gi * gg;
        creg[ul] = cc;
        h[ul] = go * th(cc);
    }

    if (hImg) {   // write h as bf16 hi/lo A-fragments at ki = gt
        int rl = r & 15, mi = r >> 4;
        char* base = hImg + gt * 8192 + mi * 512;
        #pragma unroll
        for (int u2 = 0; u2 < 8; u2++) {
            unsigned hi32, lo32;
            bsplit2(h[2*u2], h[2*u2 + 1], hi32, lo32);
            int lane2 = (rl & 7) * 4 + (u2 & 3);
            int p4 = (rl >> 3) + 2 * (u2 >> 2);
            *(unsigned*)(base + lane2 * 16 + p4 * 4) = hi32;
            *(unsigned*)(base + 4096 + lane2 * 16 + p4 * 4) = lo32;
        }
    }
    if (hlast) {
        #pragma unroll
        for (int ul = 0; ul < 16; ul++) hlast[gt * 16 + ul] = h[ul];
    }
    __syncthreads();
}

// =================== persistent recurrence ===================
__global__ __launch_bounds__(128, 1) void lstm_persistent()
{
    __shared__ float Ds[128][68];
    __shared__ float bs[64];
    const int tid = threadIdx.x, cta = blockIdx.x;
    const int lyr  = cta >> 6;          // 0: layer1 worker, 1: layer0 worker
    const int half = (cta >> 5) & 1;
    const int gt   = cta & 31;

    const float* bias = lyr ? g_b0 : g_b1;
    if (tid < 64) bs[tid] = bias[(tid & 3) * 512 + gt * 16 + (tid >> 2)];
    __syncthreads();

    float creg[16];
    #pragma unroll
    for (int i = 0; i < 16; i++) creg[i] = 0.f;
    unsigned tgt = 0u;

    const char* w1 = (const char*)g_W1img + (size_t)gt * 262144;
    const char* w0 = (const char*)g_W0img + (size_t)gt * 147456;
    #define XI(t)  ((char*)g_ximg  + ((size_t)(t) * 2 + half) * 32768)
    #define H0I(s) ((char*)g_h0img + ((size_t)((s) * 2 + half)) * 262144)
    #define H1I(s) ((char*)g_h1img + ((size_t)((s) * 2 + half)) * 262144)

    // prologue: layer0(t=0) reads h0 slot1 (zeros), writes slot0
    if (lyr == 1)
        stepH(XI(0), 4, H0I(1), 32, w0, bs, creg, H0I(0), nullptr, gt, Ds);
    gbar(half, tgt);

    for (int p = 0; p < TT - 1; p++) {
        const int s = p & 1;
        if (lyr == 0)   // layer1(p): A = h0(slot s) || h1(slot s^1); writes h1 slot s
            stepH(H0I(s), 32, H1I(s ^ 1), 32, w1, bs, creg, H1I(s), nullptr, gt, Ds);
        else            // layer0(p+1): A = x(p+1) || h0(slot s); writes h0 slot s^1
            stepH(XI(p + 1), 4, H0I(s), 32, w0, bs, creg, H0I(s ^ 1), nullptr, gt, Ds);
        gbar(half, tgt);
    }

    // layer1(511): A = h0 slot1 || h1 slot0 ; fp32 output only
    if (lyr == 0)
        stepH(H0I(1), 32, H1I(0), 32, w1, bs, creg, nullptr,
              g_h1last + (size_t)(half * 128 + tid) * HH, gt, Ds);
}

// =================== final FC ===================
__global__ void fc_kernel(const float* __restrict__ fc_w, const float* __restrict__ fc_b,
                          float* __restrict__ out)
{
    const int b = blockIdx.x;
    const float* h = g_h1last + (size_t)b * HH;
    float s = 0.f;
    for (int k = threadIdx.x; k < HH; k += 128) s += h[k] * fc_w[k];
    #pragma unroll
    for (int off = 16; off > 0; off >>= 1) s += __shfl_xor_sync(0xffffffffu, s, off);
    __shared__ float ws[4];
    if ((threadIdx.x & 31) == 0) ws[threadIdx.x >> 5] = s;
    __syncthreads();
    if (threadIdx.x == 0) out[b] = ws[0] + ws[1] + ws[2] + ws[3] + fc_b[0];
}

extern "C" void kernel_launch(void* const* d_in, const int* in_sizes, int n_in,
                              void* d_out, int out_size)
{
    const float* x   = (const float*)d_in[0];
    const float* wi0 = (const float*)d_in[1];
    const float* wh0 = (const float*)d_in[2];
    const float* bi0 = (const float*)d_in[3];
    const float* bh0 = (const float*)d_in[4];
    const float* bi1_ = nullptr; (void)bi1_;
    const float* wi1 = (const float*)d_in[5];
    const float* wh1 = (const float*)d_in[6];
    const float* bi1 = (const float*)d_in[7];
    const float* bh1 = (const float*)d_in[8];
    const float* fcw = (const float*)d_in[9];
    const float* fcb = (const float*)d_in[10];
    float* out = (float*)d_out;

    pack_kernel<<<1024, 256>>>(x, wi0, wh0, bi0, bh0, wi1, wh1, bi1, bh1);
    lstm_persistent<<<128, 128>>>();
    fc_kernel<<<BB, 128>>>(fcw, fcb, out);
}

// round 10
// speedup vs baseline: 4.7576x; 1.1192x over previous
#include <cuda_runtime.h>
#include <cuda_bf16.h>
#include <math.h>
#include <stdint.h>

#define BB 256
#define TT 512
#define HH 512
#define G4 2048

// ---- device images (static; no allocation anywhere) ----
// A-fragment image block per ki (16 k): [hi: 8 mi x 32 lane x 16B = 4KB][lo: 4KB] = 8KB
// W-fragment image block per ki:        [hi: 4 p x 32 lane x 16B = 2KB][lo: 2KB] = 4KB
__device__ uint4 g_ximg [(size_t)TT * 2 * 2048];     // [t][half] : 4 ki * 8KB = 32KB
__device__ uint4 g_W1img[(size_t)32 * 16384];        // [gt] : 64 ki * 4KB = 256KB
__device__ uint4 g_W0img[(size_t)32 * 9216];         // [gt] : 36 ki * 4KB = 144KB
__device__ uint4 g_h0img[(size_t)2 * 2 * 16384];     // [slot][half] : 32 ki * 8KB = 256KB
__device__ uint4 g_h1img[(size_t)2 * 2 * 16384];
__device__ float g_b0[G4], g_b1[G4];
__device__ float g_h1last[BB * HH];
__device__ unsigned g_cnt[2];

// fast, saturation-safe gates (slack vs 1e-3 tol is ~200x)
__device__ __forceinline__ float sg(float x) { return __fdividef(1.0f, 1.0f + __expf(-x)); }
__device__ __forceinline__ float th(float x) { return 1.0f - __fdividef(2.0f, __expf(2.0f * x) + 1.0f); }

__device__ __forceinline__ void bsplit2(float f0, float f1, unsigned& hi, unsigned& lo) {
    __nv_bfloat16 h0 = __float2bfloat16(f0), h1 = __float2bfloat16(f1);
    float r0 = f0 - __bfloat162float(h0), r1 = f1 - __bfloat162float(h1);
    __nv_bfloat16 l0 = __float2bfloat16(r0), l1 = __float2bfloat16(r1);
    hi = (unsigned)__bfloat16_as_ushort(h0) | ((unsigned)__bfloat16_as_ushort(h1) << 16);
    lo = (unsigned)__bfloat16_as_ushort(l0) | ((unsigned)__bfloat16_as_ushort(l1) << 16);
}

#define MMA(c, a, bx, by) \
    asm volatile("mma.sync.aligned.m16n8k16.row.col.f32.bf16.bf16.f32 " \
        "{%0,%1,%2,%3}, {%4,%5,%6,%7}, {%8,%9}, {%0,%1,%2,%3};" \
        : "+f"((c)[0]), "+f"((c)[1]), "+f"((c)[2]), "+f"((c)[3]) \
        : "r"((a).x), "r"((a).y), "r"((a).z), "r"((a).w), "r"(bx), "r"(by))

// =================== pack: build fragment-exact images (unchanged, proven) ===================
__global__ void pack_kernel(const float* __restrict__ x,
    const float* __restrict__ wi0, const float* __restrict__ wh0,
    const float* __restrict__ bi0, const float* __restrict__ bh0,
    const float* __restrict__ wi1, const float* __restrict__ wh1,
    const float* __restrict__ bi1, const float* __restrict__ bh1)
{
    const long long stride = (long long)gridDim.x * blockDim.x;
    const long long t0 = (long long)blockIdx.x * blockDim.x + threadIdx.x;
    if (t0 == 0) { g_cnt[0] = 0u; g_cnt[1] = 0u; }
    for (long long i = t0; i < G4; i += stride) { g_b0[i] = bi0[i] + bh0[i]; g_b1[i] = bi1[i] + bh1[i]; }
    uint4 z = make_uint4(0, 0, 0, 0);
    for (long long i = t0; i < 2 * 2 * 16384; i += stride) { g_h0img[i] = z; g_h1img[i] = z; }

    // ---- x image
    for (long long i = t0; i < (long long)TT * 2 * 4 * 8 * 32; i += stride) {
        int lane = (int)(i & 31), mi = (int)((i >> 5) & 7), ki = (int)((i >> 8) & 3);
        int half = (int)((i >> 10) & 1), t = (int)(i >> 11);
        int r0 = mi * 16 + (lane >> 2), k0 = ki * 16 + (lane & 3) * 2;
        const float* xb = x + ((size_t)(half * 128 + r0) * TT + t) * 64;
        const float* xb8 = xb + (size_t)8 * TT * 64;
        uint4 hi, lo;
        bsplit2(xb [k0],     xb [k0 + 1],     hi.x, lo.x);
        bsplit2(xb8[k0],     xb8[k0 + 1],     hi.y, lo.y);
        bsplit2(xb [k0 + 8], xb [k0 + 9],     hi.z, lo.z);
        bsplit2(xb8[k0 + 8], xb8[k0 + 9],     hi.w, lo.w);
        char* dst = (char*)g_ximg + ((size_t)t * 2 + half) * 32768 + ki * 8192 + (mi * 32 + lane) * 16;
        *(uint4*)dst = hi; *(uint4*)(dst + 4096) = lo;
    }

    // ---- W1 image
    for (long long i = t0; i < (long long)32 * 64 * 32 * 4; i += stride) {
        int p = (int)(i & 3), lane = (int)((i >> 2) & 31), ki = (int)((i >> 7) & 63), gt = (int)(i >> 13);
        int j0 = p * 16 + (lane >> 2), j1 = j0 + 8;
        int k0 = ki * 16 + (lane & 3) * 2;
        int G0 = (j0 & 3) * 512 + gt * 16 + (j0 >> 2);
        int G1 = (j1 & 3) * 512 + gt * 16 + (j1 >> 2);
        const float* s00 = (k0 < 512)     ? wi1 + (size_t)G0 * 512 + k0     : wh1 + (size_t)G0 * 512 + k0 - 512;
        const float* s08 = (k0 + 8 < 512) ? wi1 + (size_t)G0 * 512 + k0 + 8 : wh1 + (size_t)G0 * 512 + k0 + 8 - 512;
        const float* s10 = (k0 < 512)     ? wi1 + (size_t)G1 * 512 + k0     : wh1 + (size_t)G1 * 512 + k0 - 512;
        const float* s18 = (k0 + 8 < 512) ? wi1 + (size_t)G1 * 512 + k0 + 8 : wh1 + (size_t)G1 * 512 + k0 + 8 - 512;
        uint4 hi, lo;
        bsplit2(s00[0], s00[1], hi.x, lo.x);
        bsplit2(s08[0], s08[1], hi.y, lo.y);
        bsplit2(s10[0], s10[1], hi.z, lo.z);
        bsplit2(s18[0], s18[1], hi.w, lo.w);
        char* dst = (char*)g_W1img + (size_t)gt * 262144 + ki * 4096 + (p * 32 + lane) * 16;
        *(uint4*)dst = hi; *(uint4*)(dst + 2048) = lo;
    }

    // ---- W0 image: K = 576 -> 36 ki
    for (long long i = t0; i < (long long)32 * 36 * 32 * 4; i += stride) {
        int p = (int)(i & 3), lane = (int)((i >> 2) & 31);
        int rem = (int)(i >> 7); int ki = rem % 36, gt = rem / 36;
        int j0 = p * 16 + (lane >> 2), j1 = j0 + 8;
        int k0 = ki * 16 + (lane & 3) * 2;
        int G0 = (j0 & 3) * 512 + gt * 16 + (j0 >> 2);
        int G1 = (j1 & 3) * 512 + gt * 16 + (j1 >> 2);
        const float* s00 = (k0 < 64)     ? wi0 + (size_t)G0 * 64 + k0     : wh0 + (size_t)G0 * 512 + k0 - 64;
        const float* s08 = (k0 + 8 < 64) ? wi0 + (size_t)G0 * 64 + k0 + 8 : wh0 + (size_t)G0 * 512 + k0 + 8 - 64;
        const float* s10 = (k0 < 64)     ? wi0 + (size_t)G1 * 64 + k0     : wh0 + (size_t)G1 * 512 + k0 - 64;
        const float* s18 = (k0 + 8 < 64) ? wi0 + (size_t)G1 * 64 + k0 + 8 : wh0 + (size_t)G1 * 512 + k0 + 8 - 64;
        uint4 hi, lo;
        bsplit2(s00[0], s00[1], hi.x, lo.x);
        bsplit2(s08[0], s08[1], hi.y, lo.y);
        bsplit2(s10[0], s10[1], hi.z, lo.z);
        bsplit2(s18[0], s18[1], hi.w, lo.w);
        char* dst = (char*)g_W0img + (size_t)gt * 147456 + ki * 4096 + (p * 32 + lane) * 16;
        *(uint4*)dst = hi; *(uint4*)(dst + 2048) = lo;
    }
}

// =================== grid barrier (cumulative, 2 domains of 64 CTAs) ===================
__device__ __forceinline__ void gbar(int dom, unsigned& tgt)
{
    __syncthreads();
    if (threadIdx.x == 0) {
        __threadfence();
        tgt += 64;
        atomicAdd(&g_cnt[dom], 1u);
        while (*(volatile unsigned*)&g_cnt[dom] < tgt) { }
        __threadfence();
    }
    __syncthreads();
}

// =================== one layer-step: 8 warps, output col-split (no reduce) ===================
__device__ void stepH(const char* __restrict__ aA, int nA,
                      const char* __restrict__ aB, int nB,
                      const char* __restrict__ wI,
                      const float* __restrict__ bs, float* creg,
                      char* hImg, float* hlastBase, int gt, float (*Ds)[68])
{
    const int tid = threadIdx.x, lane = tid & 31;
    const int wz = (tid >> 5) & 3;       // row slice 0..3
    const int wg = tid >> 7;             // col half 0..1
    const int nCh = nA + nB;             // 36 or 64 : even
    float acc[2][4][4];
    #pragma unroll
    for (int m = 0; m < 2; m++)
        #pragma unroll
        for (int n = 0; n < 4; n++)
            #pragma unroll
            for (int q = 0; q < 4; q++) acc[m][n][q] = 0.f;

    uint4 ahA[2], alA[2], whA[2], wlA[2];
    uint4 ahB[2], alB[2], whB[2], wlB[2];

#define LDCH(S, c) do { \
    const char* ab_ = ((c) < nA) ? aA + (size_t)(c) * 8192 : aB + (size_t)((c) - nA) * 8192; \
    const char* wb_ = wI + (size_t)(c) * 4096; \
    const char* pa0_ = ab_ + ((wz * 2) * 32 + lane) * 16; \
    ah##S[0] = *(const uint4*)pa0_;          al##S[0] = *(const uint4*)(pa0_ + 4096); \
    ah##S[1] = *(const uint4*)(pa0_ + 512);  al##S[1] = *(const uint4*)(pa0_ + 512 + 4096); \
    _Pragma("unroll") \
    for (int p_ = 0; p_ < 2; p_++) { \
        const char* pw_ = wb_ + ((wg * 2 + p_) * 32 + lane) * 16; \
        wh##S[p_] = *(const uint4*)pw_;  wl##S[p_] = *(const uint4*)(pw_ + 2048); \
    } \
} while (0)

#define MMACH(S) do { \
    _Pragma("unroll") \
    for (int m_ = 0; m_ < 2; m_++) \
        _Pragma("unroll") \
        for (int p_ = 0; p_ < 2; p_++) { \
            MMA(acc[m_][2*p_],   ah##S[m_], wh##S[p_].x, wh##S[p_].y); \
            MMA(acc[m_][2*p_+1], ah##S[m_], wh##S[p_].z, wh##S[p_].w); \
        } \
    _Pragma("unroll") \
    for (int m_ = 0; m_ < 2; m_++) \
        _Pragma("unroll") \
        for (int p_ = 0; p_ < 2; p_++) { \
            MMA(acc[m_][2*p_],   ah##S[m_], wl##S[p_].x, wl##S[p_].y); \
            MMA(acc[m_][2*p_+1], ah##S[m_], wl##S[p_].z, wl##S[p_].w); \
        } \
    _Pragma("unroll") \
    for (int m_ = 0; m_ < 2; m_++) \
        _Pragma("unroll") \
        for (int p_ = 0; p_ < 2; p_++) { \
            MMA(acc[m_][2*p_],   al##S[m_], wh##S[p_].x, wh##S[p_].y); \
            MMA(acc[m_][2*p_+1], al##S[m_], wh##S[p_].z, wh##S[p_].w); \
        } \
} while (0)

    LDCH(A, 0);
    for (int c = 0; c < nCh; c += 2) {
        LDCH(B, c + 1);
        MMACH(A);
        if (c + 2 < nCh) LDCH(A, c + 2);
        MMACH(B);
    }
#undef LDCH
#undef MMACH

    // ---- stage D to SMEM (row-major) ----
    #pragma unroll
    for (int m = 0; m < 2; m++)
        #pragma unroll
        for (int n = 0; n < 4; n++) {
            int r0 = wz * 32 + m * 16 + (lane >> 2);
            int c0 = (wg * 4 + n) * 8 + (lane & 3) * 2;
            Ds[r0][c0]     = acc[m][n][0];
            Ds[r0][c0 + 1] = acc[m][n][1];
            Ds[r0 + 8][c0]     = acc[m][n][2];
            Ds[r0 + 8][c0 + 1] = acc[m][n][3];
        }
    __syncthreads();

    // ---- gate math: thread owns row tid>>1, unit-half tid&1 (8 units) ----
    const int r  = tid >> 1;
    const int uh = tid & 1;
    float h[8];
    #pragma unroll
    for (int i = 0; i < 8; i++) {
        int ul = uh * 8 + i;
        float gi = sg(Ds[r][4*ul + 0] + bs[4*ul + 0]);
        float gf = sg(Ds[r][4*ul + 1] + bs[4*ul + 1]);
        float gg = th(Ds[r][4*ul + 2] + bs[4*ul + 2]);
        float go = sg(Ds[r][4*ul + 3] + bs[4*ul + 3]);
        float cc = gf * creg[i] + gi * gg;
        creg[i] = cc;
        h[i] = go * th(cc);
    }

    if (hImg) {   // write h as bf16 hi/lo A-fragments at ki = gt
        int rl = r & 15, mi = r >> 4;
        char* base = hImg + gt * 8192 + mi * 512;
        #pragma unroll
        for (int j = 0; j < 4; j++) {          // pair index within this thread
            unsigned hi32, lo32;
            bsplit2(h[2*j], h[2*j + 1], hi32, lo32);
            int lane2 = (rl & 7) * 4 + j;      // global u2 = uh*4 + j ; u2&3 = j
            int p4 = (rl >> 3) + 2 * uh;       // u2>>2 = uh
            *(unsigned*)(base + lane2 * 16 + p4 * 4) = hi32;
            *(unsigned*)(base + 4096 + lane2 * 16 + p4 * 4) = lo32;
        }
    }
    if (hlastBase) {
        float* dst = hlastBase + (size_t)r * HH + gt * 16 + uh * 8;
        #pragma unroll
        for (int i = 0; i < 8; i++) dst[i] = h[i];
    }
    __syncthreads();
}

// =================== persistent recurrence ===================
__global__ __launch_bounds__(256, 1) void lstm_persistent()
{
    __shared__ float Ds[128][68];
    __shared__ float bs[64];
    const int tid = threadIdx.x, cta = blockIdx.x;
    const int lyr  = cta >> 6;          // 0: layer1 worker, 1: layer0 worker
    const int half = (cta >> 5) & 1;
    const int gt   = cta & 31;

    const float* bias = lyr ? g_b0 : g_b1;
    if (tid < 64) bs[tid] = bias[(tid & 3) * 512 + gt * 16 + (tid >> 2)];
    __syncthreads();

    float creg[8];
    #pragma unroll
    for (int i = 0; i < 8; i++) creg[i] = 0.f;
    unsigned tgt = 0u;

    const char* w1 = (const char*)g_W1img + (size_t)gt * 262144;
    const char* w0 = (const char*)g_W0img + (size_t)gt * 147456;
    #define XI(t)  ((char*)g_ximg  + ((size_t)(t) * 2 + half) * 32768)
    #define H0I(s) ((char*)g_h0img + ((size_t)((s) * 2 + half)) * 262144)
    #define H1I(s) ((char*)g_h1img + ((size_t)((s) * 2 + half)) * 262144)

    // prologue: layer0(t=0) reads h0 slot1 (zeros), writes slot0
    if (lyr == 1)
        stepH(XI(0), 4, H0I(1), 32, w0, bs, creg, H0I(0), nullptr, gt, Ds);
    gbar(half, tgt);

    for (int p = 0; p < TT - 1; p++) {
        const int s = p & 1;
        if (lyr == 0)   // layer1(p): A = h0(slot s) || h1(slot s^1); writes h1 slot s
            stepH(H0I(s), 32, H1I(s ^ 1), 32, w1, bs, creg, H1I(s), nullptr, gt, Ds);
        else            // layer0(p+1): A = x(p+1) || h0(slot s); writes h0 slot s^1
            stepH(XI(p + 1), 4, H0I(s), 32, w0, bs, creg, H0I(s ^ 1), nullptr, gt, Ds);
        gbar(half, tgt);
    }

    // layer1(511): A = h0 slot1 || h1 slot0 ; fp32 output only
    if (lyr == 0)
        stepH(H0I(1), 32, H1I(0), 32, w1, bs, creg, nullptr,
              g_h1last + (size_t)half * 128 * HH, gt, Ds);
}

// =================== final FC ===================
__global__ void fc_kernel(const float* __restrict__ fc_w, const float* __restrict__ fc_b,
                          float* __restrict__ out)
{
    const int b = blockIdx.x;
    const float* h = g_h1last + (size_t)b * HH;
    float s = 0.f;
    for (int k = threadIdx.x; k < HH; k += 128) s += h[k] * fc_w[k];
    #pragma unroll
    for (int off = 16; off > 0; off >>= 1) s += __shfl_xor_sync(0xffffffffu, s, off);
    __shared__ float ws[4];
    if ((threadIdx.x & 31) == 0) ws[threadIdx.x >> 5] = s;
    __syncthreads();
    if (threadIdx.x == 0) out[b] = ws[0] + ws[1] + ws[2] + ws[3] + fc_b[0];
}

extern "C" void kernel_launch(void* const* d_in, const int* in_sizes, int n_in,
                              void* d_out, int out_size)
{
    const float* x   = (const float*)d_in[0];
    const float* wi0 = (const float*)d_in[1];
    const float* wh0 = (const float*)d_in[2];
    const float* bi0 = (const float*)d_in[3];
    const float* bh0 = (const float*)d_in[4];
    const float* wi1 = (const float*)d_in[5];
    const float* wh1 = (const float*)d_in[6];
    const float* bi1 = (const float*)d_in[7];
    const float* bh1 = (const float*)d_in[8];
    const float* fcw = (const float*)d_in[9];
    const float* fcb = (const float*)d_in[10];
    float* out = (float*)d_out;

    pack_kernel<<<1024, 256>>>(x, wi0, wh0, bi0, bh0, wi1, wh1, bi1, bh1);
    lstm_persistent<<<128, 256>>>();
    fc_kernel<<<BB, 128>>>(fcw, fcb, out);
}

// round 11
// speedup vs baseline: 7.0202x; 1.4756x over previous
#include <cuda_runtime.h>
#include <cuda_fp16.h>
#include <math.h>
#include <stdint.h>

#define BB 256
#define TT 512
#define HH 512
#define G4 2048
#define LSC 1024.0f          // Wl scale
#define LSCI 0.0009765625f   // 1/1024

// ---- device images (static; no allocation anywhere) ----
// A-fragment image per ki (16 k): 8 mi x 32 lane x 16B = 4KB  (single fp16 plane)
// W-fragment image per ki: [hi: 4 p x 32 lane x 16B = 2KB][lo(scaled): 2KB] = 4KB
__device__ uint4 g_ximg [(size_t)TT * 2 * 1024];     // [t][half] : 4 ki * 4KB = 16KB
__device__ uint4 g_W1img[(size_t)32 * 16384];        // [gt] : 64 ki * 4KB = 256KB
__device__ uint4 g_W0img[(size_t)32 * 9216];         // [gt] : 36 ki * 4KB = 144KB
__device__ uint4 g_h0img[(size_t)2 * 2 * 8192];      // [slot][half] : 32 ki * 4KB = 128KB
__device__ uint4 g_h1img[(size_t)2 * 2 * 8192];
__device__ float g_b0[G4], g_b1[G4];
__device__ float g_h1last[BB * HH];
__device__ unsigned g_cnt[2];

// fast, saturation-safe gates
__device__ __forceinline__ float sg(float x) { return __fdividef(1.0f, 1.0f + __expf(-x)); }
__device__ __forceinline__ float th(float x) { return 1.0f - __fdividef(2.0f, __expf(2.0f * x) + 1.0f); }

__device__ __forceinline__ unsigned fpk2(float a, float b) {
    __half2 h = __floats2half2_rn(a, b);
    return *reinterpret_cast<unsigned*>(&h);
}
// W split: hi = fp16(w), lo = fp16((w - hi) * 1024)  (lo stays normal-range)
__device__ __forceinline__ void wsplit2(float a, float b, unsigned& hi, unsigned& lo) {
    __half ha = __float2half_rn(a), hb = __float2half_rn(b);
    float ra = (a - __half2float(ha)) * LSC;
    float rb = (b - __half2float(hb)) * LSC;
    hi = (unsigned)__half_as_ushort(ha) | ((unsigned)__half_as_ushort(hb) << 16);
    lo = fpk2(ra, rb);
}

#define MMA(c, a, bx, by) \
    asm volatile("mma.sync.aligned.m16n8k16.row.col.f32.f16.f16.f32 " \
        "{%0,%1,%2,%3}, {%4,%5,%6,%7}, {%8,%9}, {%0,%1,%2,%3};" \
        : "+f"((c)[0]), "+f"((c)[1]), "+f"((c)[2]), "+f"((c)[3]) \
        : "r"((a).x), "r"((a).y), "r"((a).z), "r"((a).w), "r"(bx), "r"(by))

// =================== pack: build fragment-exact images ===================
__global__ void pack_kernel(const float* __restrict__ x,
    const float* __restrict__ wi0, const float* __restrict__ wh0,
    const float* __restrict__ bi0, const float* __restrict__ bh0,
    const float* __restrict__ wi1, const float* __restrict__ wh1,
    const float* __restrict__ bi1, const float* __restrict__ bh1)
{
    const long long stride = (long long)gridDim.x * blockDim.x;
    const long long t0 = (long long)blockIdx.x * blockDim.x + threadIdx.x;
    if (t0 == 0) { g_cnt[0] = 0u; g_cnt[1] = 0u; }
    for (long long i = t0; i < G4; i += stride) { g_b0[i] = bi0[i] + bh0[i]; g_b1[i] = bi1[i] + bh1[i]; }
    uint4 z = make_uint4(0, 0, 0, 0);
    for (long long i = t0; i < 2 * 2 * 8192; i += stride) { g_h0img[i] = z; g_h1img[i] = z; }

    // ---- x image (fp16 single plane): i = (((t*2+half)*4+ki)*8+mi)*32+lane
    for (long long i = t0; i < (long long)TT * 2 * 4 * 8 * 32; i += stride) {
        int lane = (int)(i & 31), mi = (int)((i >> 5) & 7), ki = (int)((i >> 8) & 3);
        int half = (int)((i >> 10) & 1), t = (int)(i >> 11);
        int r0 = mi * 16 + (lane >> 2), k0 = ki * 16 + (lane & 3) * 2;
        const float* xb = x + ((size_t)(half * 128 + r0) * TT + t) * 64;
        const float* xb8 = xb + (size_t)8 * TT * 64;
        uint4 hi;
        hi.x = fpk2(xb [k0],     xb [k0 + 1]);
        hi.y = fpk2(xb8[k0],     xb8[k0 + 1]);
        hi.z = fpk2(xb [k0 + 8], xb [k0 + 9]);
        hi.w = fpk2(xb8[k0 + 8], xb8[k0 + 9]);
        char* dst = (char*)g_ximg + ((size_t)t * 2 + half) * 16384 + ki * 4096 + (mi * 32 + lane) * 16;
        *(uint4*)dst = hi;
    }

    // ---- W1 image (fp16 hi + scaled lo)
    for (long long i = t0; i < (long long)32 * 64 * 32 * 4; i += stride) {
        int p = (int)(i & 3), lane = (int)((i >> 2) & 31), ki = (int)((i >> 7) & 63), gt = (int)(i >> 13);
        int j0 = p * 16 + (lane >> 2), j1 = j0 + 8;
        int k0 = ki * 16 + (lane & 3) * 2;
        int G0 = (j0 & 3) * 512 + gt * 16 + (j0 >> 2);
        int G1 = (j1 & 3) * 512 + gt * 16 + (j1 >> 2);
        const float* s00 = (k0 < 512)     ? wi1 + (size_t)G0 * 512 + k0     : wh1 + (size_t)G0 * 512 + k0 - 512;
        const float* s08 = (k0 + 8 < 512) ? wi1 + (size_t)G0 * 512 + k0 + 8 : wh1 + (size_t)G0 * 512 + k0 + 8 - 512;
        const float* s10 = (k0 < 512)     ? wi1 + (size_t)G1 * 512 + k0     : wh1 + (size_t)G1 * 512 + k0 - 512;
        const float* s18 = (k0 + 8 < 512) ? wi1 + (size_t)G1 * 512 + k0 + 8 : wh1 + (size_t)G1 * 512 + k0 + 8 - 512;
        uint4 hi, lo;
        wsplit2(s00[0], s00[1], hi.x, lo.x);
        wsplit2(s08[0], s08[1], hi.y, lo.y);
        wsplit2(s10[0], s10[1], hi.z, lo.z);
        wsplit2(s18[0], s18[1], hi.w, lo.w);
        char* dst = (char*)g_W1img + (size_t)gt * 262144 + ki * 4096 + (p * 32 + lane) * 16;
        *(uint4*)dst = hi; *(uint4*)(dst + 2048) = lo;
    }

    // ---- W0 image: K = 576 -> 36 ki
    for (long long i = t0; i < (long long)32 * 36 * 32 * 4; i += stride) {
        int p = (int)(i & 3), lane = (int)((i >> 2) & 31);
        int rem = (int)(i >> 7); int ki = rem % 36, gt = rem / 36;
        int j0 = p * 16 + (lane >> 2), j1 = j0 + 8;
        int k0 = ki * 16 + (lane & 3) * 2;
        int G0 = (j0 & 3) * 512 + gt * 16 + (j0 >> 2);
        int G1 = (j1 & 3) * 512 + gt * 16 + (j1 >> 2);
        const float* s00 = (k0 < 64)     ? wi0 + (size_t)G0 * 64 + k0     : wh0 + (size_t)G0 * 512 + k0 - 64;
        const float* s08 = (k0 + 8 < 64) ? wi0 + (size_t)G0 * 64 + k0 + 8 : wh0 + (size_t)G0 * 512 + k0 + 8 - 64;
        const float* s10 = (k0 < 64)     ? wi0 + (size_t)G1 * 64 + k0     : wh0 + (size_t)G1 * 512 + k0 - 64;
        const float* s18 = (k0 + 8 < 64) ? wi0 + (size_t)G1 * 64 + k0 + 8 : wh0 + (size_t)G1 * 512 + k0 + 8 - 64;
        uint4 hi, lo;
        wsplit2(s00[0], s00[1], hi.x, lo.x);
        wsplit2(s08[0], s08[1], hi.y, lo.y);
        wsplit2(s10[0], s10[1], hi.z, lo.z);
        wsplit2(s18[0], s18[1], hi.w, lo.w);
        char* dst = (char*)g_W0img + (size_t)gt * 147456 + ki * 4096 + (p * 32 + lane) * 16;
        *(uint4*)dst = hi; *(uint4*)(dst + 2048) = lo;
    }
}

// =================== grid barrier (cumulative, 2 domains of 64 CTAs) ===================
__device__ __forceinline__ void gbar(int dom, unsigned& tgt)
{
    __syncthreads();
    if (threadIdx.x == 0) {
        __threadfence();
        tgt += 64;
        atomicAdd(&g_cnt[dom], 1u);
        while (*(volatile unsigned*)&g_cnt[dom] < tgt) { }
        __threadfence();
    }
    __syncthreads();
}

// =================== one layer-step: 8 warps, output col-split ===================
__device__ void stepH(const char* __restrict__ aA, int nA,
                      const char* __restrict__ aB, int nB,
                      const char* __restrict__ wI,
                      const float* __restrict__ bs, float* creg,
                      char* hImg, float* hlastBase, int gt, float (*Ds)[68])
{
    const int tid = threadIdx.x, lane = tid & 31;
    const int wz = (tid >> 5) & 3;       // row slice 0..3
    const int wg = tid >> 7;             // col half 0..1
    const int nCh = nA + nB;             // 36 or 64 : even
    float accH[2][4][4], accL[2][4][4];
    #pragma unroll
    for (int m = 0; m < 2; m++)
        #pragma unroll
        for (int n = 0; n < 4; n++)
            #pragma unroll
            for (int q = 0; q < 4; q++) { accH[m][n][q] = 0.f; accL[m][n][q] = 0.f; }

    uint4 ahA[2], whA[2], wlA[2];
    uint4 ahB[2], whB[2], wlB[2];

#define LDCH(S, c) do { \
    const char* ab_ = ((c) < nA) ? aA + (size_t)(c) * 4096 : aB + (size_t)((c) - nA) * 4096; \
    const char* wb_ = wI + (size_t)(c) * 4096; \
    const char* pa0_ = ab_ + ((wz * 2) * 32 + lane) * 16; \
    ah##S[0] = *(const uint4*)pa0_; \
    ah##S[1] = *(const uint4*)(pa0_ + 512); \
    _Pragma("unroll") \
    for (int p_ = 0; p_ < 2; p_++) { \
        const char* pw_ = wb_ + ((wg * 2 + p_) * 32 + lane) * 16; \
        wh##S[p_] = *(const uint4*)pw_;  wl##S[p_] = *(const uint4*)(pw_ + 2048); \
    } \
} while (0)

#define MMACH(S) do { \
    _Pragma("unroll") \
    for (int m_ = 0; m_ < 2; m_++) \
        _Pragma("unroll") \
        for (int p_ = 0; p_ < 2; p_++) { \
            MMA(accH[m_][2*p_],   ah##S[m_], wh##S[p_].x, wh##S[p_].y); \
            MMA(accH[m_][2*p_+1], ah##S[m_], wh##S[p_].z, wh##S[p_].w); \
        } \
    _Pragma("unroll") \
    for (int m_ = 0; m_ < 2; m_++) \
        _Pragma("unroll") \
        for (int p_ = 0; p_ < 2; p_++) { \
            MMA(accL[m_][2*p_],   ah##S[m_], wl##S[p_].x, wl##S[p_].y); \
            MMA(accL[m_][2*p_+1], ah##S[m_], wl##S[p_].z, wl##S[p_].w); \
        } \
} while (0)

    LDCH(A, 0);
    for (int c = 0; c < nCh; c += 2) {
        LDCH(B, c + 1);
        MMACH(A);
        if (c + 2 < nCh) LDCH(A, c + 2);
        MMACH(B);
    }
#undef LDCH
#undef MMACH

    // ---- stage combined D to SMEM (row-major) ----
    #pragma unroll
    for (int m = 0; m < 2; m++)
        #pragma unroll
        for (int n = 0; n < 4; n++) {
            int r0 = wz * 32 + m * 16 + (lane >> 2);
            int c0 = (wg * 4 + n) * 8 + (lane & 3) * 2;
            Ds[r0][c0]     = accH[m][n][0] + LSCI * accL[m][n][0];
            Ds[r0][c0 + 1] = accH[m][n][1] + LSCI * accL[m][n][1];
            Ds[r0 + 8][c0]     = accH[m][n][2] + LSCI * accL[m][n][2];
            Ds[r0 + 8][c0 + 1] = accH[m][n][3] + LSCI * accL[m][n][3];
        }
    __syncthreads();

    // ---- gate math: thread owns row tid>>1, unit-half tid&1 (8 units) ----
    const int r  = tid >> 1;
    const int uh = tid & 1;
    float h[8];
    #pragma unroll
    for (int i = 0; i < 8; i++) {
        int ul = uh * 8 + i;
        float gi = sg(Ds[r][4*ul + 0] + bs[4*ul + 0]);
        float gf = sg(Ds[r][4*ul + 1] + bs[4*ul + 1]);
        float gg = th(Ds[r][4*ul + 2] + bs[4*ul + 2]);
        float go = sg(Ds[r][4*ul + 3] + bs[4*ul + 3]);
        float cc = gf * creg[i] + gi * gg;
        creg[i] = cc;
        h[i] = go * th(cc);
    }

    if (hImg) {   // write h as fp16 A-fragments at ki = gt (single plane)
        int rl = r & 15, mi = r >> 4;
        char* base = hImg + gt * 4096 + mi * 512;
        #pragma unroll
        for (int j = 0; j < 4; j++) {
            unsigned hi32 = fpk2(h[2*j], h[2*j + 1]);
            int lane2 = (rl & 7) * 4 + j;      // u2 = uh*4+j ; u2&3 = j
            int p4 = (rl >> 3) + 2 * uh;       // u2>>2 = uh
            *(unsigned*)(base + lane2 * 16 + p4 * 4) = hi32;
        }
    }
    if (hlastBase) {
        float* dst = hlastBase + (size_t)r * HH + gt * 16 + uh * 8;
        #pragma unroll
        for (int i = 0; i < 8; i++) dst[i] = h[i];
    }
    __syncthreads();
}

// =================== persistent recurrence ===================
__global__ __launch_bounds__(256, 1) void lstm_persistent()
{
    __shared__ float Ds[128][68];
    __shared__ float bs[64];
    const int tid = threadIdx.x, cta = blockIdx.x;
    const int lyr  = cta >> 6;          // 0: layer1 worker, 1: layer0 worker
    const int half = (cta >> 5) & 1;
    const int gt   = cta & 31;

    const float* bias = lyr ? g_b0 : g_b1;
    if (tid < 64) bs[tid] = bias[(tid & 3) * 512 + gt * 16 + (tid >> 2)];
    __syncthreads();

    float creg[8];
    #pragma unroll
    for (int i = 0; i < 8; i++) creg[i] = 0.f;
    unsigned tgt = 0u;

    const char* w1 = (const char*)g_W1img + (size_t)gt * 262144;
    const char* w0 = (const char*)g_W0img + (size_t)gt * 147456;
    #define XI(t)  ((char*)g_ximg  + ((size_t)(t) * 2 + half) * 16384)
    #define H0I(s) ((char*)g_h0img + ((size_t)((s) * 2 + half)) * 131072)
    #define H1I(s) ((char*)g_h1img + ((size_t)((s) * 2 + half)) * 131072)

    // prologue: layer0(t=0) reads h0 slot1 (zeros), writes slot0
    if (lyr == 1)
        stepH(XI(0), 4, H0I(1), 32, w0, bs, creg, H0I(0), nullptr, gt, Ds);
    gbar(half, tgt);

    for (int p = 0; p < TT - 1; p++) {
        const int s = p & 1;
        if (lyr == 0)   // layer1(p): A = h0(slot s) || h1(slot s^1); writes h1 slot s
            stepH(H0I(s), 32, H1I(s ^ 1), 32, w1, bs, creg, H1I(s), nullptr, gt, Ds);
        else            // layer0(p+1): A = x(p+1) || h0(slot s); writes h0 slot s^1
            stepH(XI(p + 1), 4, H0I(s), 32, w0, bs, creg, H0I(s ^ 1), nullptr, gt, Ds);
        gbar(half, tgt);
    }

    // layer1(511): A = h0 slot1 || h1 slot0 ; fp32 output only
    if (lyr == 0)
        stepH(H0I(1), 32, H1I(0), 32, w1, bs, creg, nullptr,
              g_h1last + (size_t)half * 128 * HH, gt, Ds);
}

// =================== final FC ===================
__global__ void fc_kernel(const float* __restrict__ fc_w, const float* __restrict__ fc_b,
                          float* __restrict__ out)
{
    const int b = blockIdx.x;
    const float* h = g_h1last + (size_t)b * HH;
    float s = 0.f;
    for (int k = threadIdx.x; k < HH; k += 128) s += h[k] * fc_w[k];
    #pragma unroll
    for (int off = 16; off > 0; off >>= 1) s += __shfl_xor_sync(0xffffffffu, s, off);
    __shared__ float ws[4];
    if ((threadIdx.x & 31) == 0) ws[threadIdx.x >> 5] = s;
    __syncthreads();
    if (threadIdx.x == 0) out[b] = ws[0] + ws[1] + ws[2] + ws[3] + fc_b[0];
}

extern "C" void kernel_launch(void* const* d_in, const int* in_sizes, int n_in,
                              void* d_out, int out_size)
{
    const float* x   = (const float*)d_in[0];
    const float* wi0 = (const float*)d_in[1];
    const float* wh0 = (const float*)d_in[2];
    const float* bi0 = (const float*)d_in[3];
    const float* bh0 = (const float*)d_in[4];
    const float* wi1 = (const float*)d_in[5];
    const float* wh1 = (const float*)d_in[6];
    const float* bi1 = (const float*)d_in[7];
    const float* bh1 = (const float*)d_in[8];
    const float* fcw = (const float*)d_in[9];
    const float* fcb = (const float*)d_in[10];
    float* out = (float*)d_out;

    pack_kernel<<<1024, 256>>>(x, wi0, wh0, bi0, bh0, wi1, wh1, bi1, bh1);
    lstm_persistent<<<128, 256>>>();
    fc_kernel<<<BB, 128>>>(fcw, fcb, out);
}

// round 12
// speedup vs baseline: 8.8994x; 1.2677x over previous
#include <cuda_runtime.h>
#include <cuda_fp16.h>
#include <math.h>
#include <stdint.h>

#define BB 256
#define TT 512
#define HH 512
#define G4 2048
#define LSC 1024.0f          // Wl scale (kept in pack; unused in hot loop)

// ---- device images (static; no allocation anywhere) ----
// A-fragment image per ki (16 k): 8 mi x 32 lane x 16B = 4KB  (single fp16 plane)
// W-fragment image per ki: [hi: 4 p x 32 lane x 16B = 2KB][lo(scaled): 2KB] = 4KB
__device__ uint4 g_ximg [(size_t)TT * 2 * 1024];     // [t][half] : 4 ki * 4KB = 16KB
__device__ uint4 g_W1img[(size_t)32 * 16384];        // [gt] : 64 ki * 4KB = 256KB
__device__ uint4 g_W0img[(size_t)32 * 9216];         // [gt] : 36 ki * 4KB = 144KB
__device__ uint4 g_h0img[(size_t)2 * 2 * 8192];      // [slot][half] : 32 ki * 4KB = 128KB
__device__ uint4 g_h1img[(size_t)2 * 2 * 8192];
__device__ float g_b0[G4], g_b1[G4];
__device__ float g_h1last[BB * HH];
__device__ unsigned g_cnt[2];

// fast, saturation-safe gates
__device__ __forceinline__ float sg(float x) { return __fdividef(1.0f, 1.0f + __expf(-x)); }
__device__ __forceinline__ float th(float x) { return 1.0f - __fdividef(2.0f, __expf(2.0f * x) + 1.0f); }

__device__ __forceinline__ unsigned fpk2(float a, float b) {
    __half2 h = __floats2half2_rn(a, b);
    return *reinterpret_cast<unsigned*>(&h);
}
// W split: hi = fp16(w), lo = fp16((w - hi) * 1024)  (lo plane retained for fallback)
__device__ __forceinline__ void wsplit2(float a, float b, unsigned& hi, unsigned& lo) {
    __half ha = __float2half_rn(a), hb = __float2half_rn(b);
    float ra = (a - __half2float(ha)) * LSC;
    float rb = (b - __half2float(hb)) * LSC;
    hi = (unsigned)__half_as_ushort(ha) | ((unsigned)__half_as_ushort(hb) << 16);
    lo = fpk2(ra, rb);
}

#define MMA(c, a, bx, by) \
    asm volatile("mma.sync.aligned.m16n8k16.row.col.f32.f16.f16.f32 " \
        "{%0,%1,%2,%3}, {%4,%5,%6,%7}, {%8,%9}, {%0,%1,%2,%3};" \
        : "+f"((c)[0]), "+f"((c)[1]), "+f"((c)[2]), "+f"((c)[3]) \
        : "r"((a).x), "r"((a).y), "r"((a).z), "r"((a).w), "r"(bx), "r"(by))

// =================== pack: build fragment-exact images (unchanged, proven) ===================
__global__ void pack_kernel(const float* __restrict__ x,
    const float* __restrict__ wi0, const float* __restrict__ wh0,
    const float* __restrict__ bi0, const float* __restrict__ bh0,
    const float* __restrict__ wi1, const float* __restrict__ wh1,
    const float* __restrict__ bi1, const float* __restrict__ bh1)
{
    const long long stride = (long long)gridDim.x * blockDim.x;
    const long long t0 = (long long)blockIdx.x * blockDim.x + threadIdx.x;
    if (t0 == 0) { g_cnt[0] = 0u; g_cnt[1] = 0u; }
    for (long long i = t0; i < G4; i += stride) { g_b0[i] = bi0[i] + bh0[i]; g_b1[i] = bi1[i] + bh1[i]; }
    uint4 z = make_uint4(0, 0, 0, 0);
    for (long long i = t0; i < 2 * 2 * 8192; i += stride) { g_h0img[i] = z; g_h1img[i] = z; }

    // ---- x image (fp16 single plane)
    for (long long i = t0; i < (long long)TT * 2 * 4 * 8 * 32; i += stride) {
        int lane = (int)(i & 31), mi = (int)((i >> 5) & 7), ki = (int)((i >> 8) & 3);
        int half = (int)((i >> 10) & 1), t = (int)(i >> 11);
        int r0 = mi * 16 + (lane >> 2), k0 = ki * 16 + (lane & 3) * 2;
        const float* xb = x + ((size_t)(half * 128 + r0) * TT + t) * 64;
        const float* xb8 = xb + (size_t)8 * TT * 64;
        uint4 hi;
        hi.x = fpk2(xb [k0],     xb [k0 + 1]);
        hi.y = fpk2(xb8[k0],     xb8[k0 + 1]);
        hi.z = fpk2(xb [k0 + 8], xb [k0 + 9]);
        hi.w = fpk2(xb8[k0 + 8], xb8[k0 + 9]);
        char* dst = (char*)g_ximg + ((size_t)t * 2 + half) * 16384 + ki * 4096 + (mi * 32 + lane) * 16;
        *(uint4*)dst = hi;
    }

    // ---- W1 image (fp16 hi + scaled lo)
    for (long long i = t0; i < (long long)32 * 64 * 32 * 4; i += stride) {
        int p = (int)(i & 3), lane = (int)((i >> 2) & 31), ki = (int)((i >> 7) & 63), gt = (int)(i >> 13);
        int j0 = p * 16 + (lane >> 2), j1 = j0 + 8;
        int k0 = ki * 16 + (lane & 3) * 2;
        int G0 = (j0 & 3) * 512 + gt * 16 + (j0 >> 2);
        int G1 = (j1 & 3) * 512 + gt * 16 + (j1 >> 2);
        const float* s00 = (k0 < 512)     ? wi1 + (size_t)G0 * 512 + k0     : wh1 + (size_t)G0 * 512 + k0 - 512;
        const float* s08 = (k0 + 8 < 512) ? wi1 + (size_t)G0 * 512 + k0 + 8 : wh1 + (size_t)G0 * 512 + k0 + 8 - 512;
        const float* s10 = (k0 < 512)     ? wi1 + (size_t)G1 * 512 + k0     : wh1 + (size_t)G1 * 512 + k0 - 512;
        const float* s18 = (k0 + 8 < 512) ? wi1 + (size_t)G1 * 512 + k0 + 8 : wh1 + (size_t)G1 * 512 + k0 + 8 - 512;
        uint4 hi, lo;
        wsplit2(s00[0], s00[1], hi.x, lo.x);
        wsplit2(s08[0], s08[1], hi.y, lo.y);
        wsplit2(s10[0], s10[1], hi.z, lo.z);
        wsplit2(s18[0], s18[1], hi.w, lo.w);
        char* dst = (char*)g_W1img + (size_t)gt * 262144 + ki * 4096 + (p * 32 + lane) * 16;
        *(uint4*)dst = hi; *(uint4*)(dst + 2048) = lo;
    }

    // ---- W0 image: K = 576 -> 36 ki
    for (long long i = t0; i < (long long)32 * 36 * 32 * 4; i += stride) {
        int p = (int)(i & 3), lane = (int)((i >> 2) & 31);
        int rem = (int)(i >> 7); int ki = rem % 36, gt = rem / 36;
        int j0 = p * 16 + (lane >> 2), j1 = j0 + 8;
        int k0 = ki * 16 + (lane & 3) * 2;
        int G0 = (j0 & 3) * 512 + gt * 16 + (j0 >> 2);
        int G1 = (j1 & 3) * 512 + gt * 16 + (j1 >> 2);
        const float* s00 = (k0 < 64)     ? wi0 + (size_t)G0 * 64 + k0     : wh0 + (size_t)G0 * 512 + k0 - 64;
        const float* s08 = (k0 + 8 < 64) ? wi0 + (size_t)G0 * 64 + k0 + 8 : wh0 + (size_t)G0 * 512 + k0 + 8 - 64;
        const float* s10 = (k0 < 64)     ? wi0 + (size_t)G1 * 64 + k0     : wh0 + (size_t)G1 * 512 + k0 - 64;
        const float* s18 = (k0 + 8 < 64) ? wi0 + (size_t)G1 * 64 + k0 + 8 : wh0 + (size_t)G1 * 512 + k0 + 8 - 64;
        uint4 hi, lo;
        wsplit2(s00[0], s00[1], hi.x, lo.x);
        wsplit2(s08[0], s08[1], hi.y, lo.y);
        wsplit2(s10[0], s10[1], hi.z, lo.z);
        wsplit2(s18[0], s18[1], hi.w, lo.w);
        char* dst = (char*)g_W0img + (size_t)gt * 147456 + ki * 4096 + (p * 32 + lane) * 16;
        *(uint4*)dst = hi; *(uint4*)(dst + 2048) = lo;
    }
}

// =================== grid barrier (cumulative, 2 domains of 64 CTAs) ===================
__device__ __forceinline__ void gbar(int dom, unsigned& tgt)
{
    __syncthreads();
    if (threadIdx.x == 0) {
        __threadfence();
        tgt += 64;
        atomicAdd(&g_cnt[dom], 1u);
        while (*(volatile unsigned*)&g_cnt[dom] < tgt) { }
        __threadfence();
    }
    __syncthreads();
}

// =================== one layer-step: 8 warps, output col-split, single-MMA ===================
__device__ void stepH(const char* __restrict__ aA, int nA,
                      const char* __restrict__ aB, int nB,
                      const char* __restrict__ wI,
                      const float* __restrict__ bs, float* creg,
                      char* hImg, float* hlastBase, int gt, float (*Ds)[68])
{
    const int tid = threadIdx.x, lane = tid & 31;
    const int wz = (tid >> 5) & 3;       // row slice 0..3
    const int wg = tid >> 7;             // col half 0..1
    const int nCh = nA + nB;             // 36 or 64 : even
    float accH[2][4][4];
    #pragma unroll
    for (int m = 0; m < 2; m++)
        #pragma unroll
        for (int n = 0; n < 4; n++)
            #pragma unroll
            for (int q = 0; q < 4; q++) accH[m][n][q] = 0.f;

    uint4 ahA[2], whA[2];
    uint4 ahB[2], whB[2];

#define LDCH(S, c) do { \
    const char* ab_ = ((c) < nA) ? aA + (size_t)(c) * 4096 : aB + (size_t)((c) - nA) * 4096; \
    const char* wb_ = wI + (size_t)(c) * 4096; \
    const char* pa0_ = ab_ + ((wz * 2) * 32 + lane) * 16; \
    ah##S[0] = *(const uint4*)pa0_; \
    ah##S[1] = *(const uint4*)(pa0_ + 512); \
    wh##S[0] = *(const uint4*)(wb_ + ((wg * 2 + 0) * 32 + lane) * 16); \
    wh##S[1] = *(const uint4*)(wb_ + ((wg * 2 + 1) * 32 + lane) * 16); \
} while (0)

#define MMACH(S) do { \
    _Pragma("unroll") \
    for (int m_ = 0; m_ < 2; m_++) \
        _Pragma("unroll") \
        for (int p_ = 0; p_ < 2; p_++) { \
            MMA(accH[m_][2*p_],   ah##S[m_], wh##S[p_].x, wh##S[p_].y); \
            MMA(accH[m_][2*p_+1], ah##S[m_], wh##S[p_].z, wh##S[p_].w); \
        } \
} while (0)

    LDCH(A, 0);
    for (int c = 0; c < nCh; c += 2) {
        LDCH(B, c + 1);
        MMACH(A);
        if (c + 2 < nCh) LDCH(A, c + 2);
        MMACH(B);
    }
#undef LDCH
#undef MMACH

    // ---- stage D to SMEM (row-major) ----
    #pragma unroll
    for (int m = 0; m < 2; m++)
        #pragma unroll
        for (int n = 0; n < 4; n++) {
            int r0 = wz * 32 + m * 16 + (lane >> 2);
            int c0 = (wg * 4 + n) * 8 + (lane & 3) * 2;
            Ds[r0][c0]     = accH[m][n][0];
            Ds[r0][c0 + 1] = accH[m][n][1];
            Ds[r0 + 8][c0]     = accH[m][n][2];
            Ds[r0 + 8][c0 + 1] = accH[m][n][3];
        }
    __syncthreads();

    // ---- gate math: thread owns row tid>>1, unit-half tid&1 (8 units) ----
    const int r  = tid >> 1;
    const int uh = tid & 1;
    float h[8];
    #pragma unroll
    for (int i = 0; i < 8; i++) {
        int ul = uh * 8 + i;
        float gi = sg(Ds[r][4*ul + 0] + bs[4*ul + 0]);
        float gf = sg(Ds[r][4*ul + 1] + bs[4*ul + 1]);
        float gg = th(Ds[r][4*ul + 2] + bs[4*ul + 2]);
        float go = sg(Ds[r][4*ul + 3] + bs[4*ul + 3]);
        float cc = gf * creg[i] + gi * gg;
        creg[i] = cc;
        h[i] = go * th(cc);
    }

    if (hImg) {   // write h as fp16 A-fragments at ki = gt (single plane)
        int rl = r & 15, mi = r >> 4;
        char* base = hImg + gt * 4096 + mi * 512;
        #pragma unroll
        for (int j = 0; j < 4; j++) {
            unsigned hi32 = fpk2(h[2*j], h[2*j + 1]);
            int lane2 = (rl & 7) * 4 + j;      // u2 = uh*4+j ; u2&3 = j
            int p4 = (rl >> 3) + 2 * uh;       // u2>>2 = uh
            *(unsigned*)(base + lane2 * 16 + p4 * 4) = hi32;
        }
    }
    if (hlastBase) {
        float* dst = hlastBase + (size_t)r * HH + gt * 16 + uh * 8;
        #pragma unroll
        for (int i = 0; i < 8; i++) dst[i] = h[i];
    }
    __syncthreads();
}

// =================== persistent recurrence ===================
__global__ __launch_bounds__(256, 1) void lstm_persistent()
{
    __shared__ float Ds[128][68];
    __shared__ float bs[64];
    const int tid = threadIdx.x, cta = blockIdx.x;
    const int lyr  = cta >> 6;          // 0: layer1 worker, 1: layer0 worker
    const int half = (cta >> 5) & 1;
    const int gt   = cta & 31;

    const float* bias = lyr ? g_b0 : g_b1;
    if (tid < 64) bs[tid] = bias[(tid & 3) * 512 + gt * 16 + (tid >> 2)];
    __syncthreads();

    float creg[8];
    #pragma unroll
    for (int i = 0; i < 8; i++) creg[i] = 0.f;
    unsigned tgt = 0u;

    const char* w1 = (const char*)g_W1img + (size_t)gt * 262144;
    const char* w0 = (const char*)g_W0img + (size_t)gt * 147456;
    #define XI(t)  ((char*)g_ximg  + ((size_t)(t) * 2 + half) * 16384)
    #define H0I(s) ((char*)g_h0img + ((size_t)((s) * 2 + half)) * 131072)
    #define H1I(s) ((char*)g_h1img + ((size_t)((s) * 2 + half)) * 131072)

    // prologue: layer0(t=0) reads h0 slot1 (zeros), writes slot0
    if (lyr == 1)
        stepH(XI(0), 4, H0I(1), 32, w0, bs, creg, H0I(0), nullptr, gt, Ds);
    gbar(half, tgt);

    for (int p = 0; p < TT - 1; p++) {
        const int s = p & 1;
        if (lyr == 0)   // layer1(p): A = h0(slot s) || h1(slot s^1); writes h1 slot s
            stepH(H0I(s), 32, H1I(s ^ 1), 32, w1, bs, creg, H1I(s), nullptr, gt, Ds);
        else            // layer0(p+1): A = x(p+1) || h0(slot s); writes h0 slot s^1
            stepH(XI(p + 1), 4, H0I(s), 32, w0, bs, creg, H0I(s ^ 1), nullptr, gt, Ds);
        gbar(half, tgt);
    }

    // layer1(511): A = h0 slot1 || h1 slot0 ; fp32 output only
    if (lyr == 0)
        stepH(H0I(1), 32, H1I(0), 32, w1, bs, creg, nullptr,
              g_h1last + (size_t)half * 128 * HH, gt, Ds);
}

// =================== final FC ===================
__global__ void fc_kernel(const float* __restrict__ fc_w, const float* __restrict__ fc_b,
                          float* __restrict__ out)
{
    const int b = blockIdx.x;
    const float* h = g_h1last + (size_t)b * HH;
    float s = 0.f;
    for (int k = threadIdx.x; k < HH; k += 128) s += h[k] * fc_w[k];
    #pragma unroll
    for (int off = 16; off > 0; off >>= 1) s += __shfl_xor_sync(0xffffffffu, s, off);
    __shared__ float ws[4];
    if ((threadIdx.x & 31) == 0) ws[threadIdx.x >> 5] = s;
    __syncthreads();
    if (threadIdx.x == 0) out[b] = ws[0] + ws[1] + ws[2] + ws[3] + fc_b[0];
}

extern "C" void kernel_launch(void* const* d_in, const int* in_sizes, int n_in,
                              void* d_out, int out_size)
{
    const float* x   = (const float*)d_in[0];
    const float* wi0 = (const float*)d_in[1];
    const float* wh0 = (const float*)d_in[2];
    const float* bi0 = (const float*)d_in[3];
    const float* bh0 = (const float*)d_in[4];
    const float* wi1 = (const float*)d_in[5];
    const float* wh1 = (const float*)d_in[6];
    const float* bi1 = (const float*)d_in[7];
    const float* bh1 = (const float*)d_in[8];
    const float* fcw = (const float*)d_in[9];
    const float* fcb = (const float*)d_in[10];
    float* out = (float*)d_out;

    pack_kernel<<<1024, 256>>>(x, wi0, wh0, bi0, bh0, wi1, wh1, bi1, bh1);
    lstm_persistent<<<128, 256>>>();
    fc_kernel<<<BB, 128>>>(fcw, fcb, out);
}

// round 13
// speedup vs baseline: 10.3379x; 1.1616x over previous
#include <cuda_runtime.h>
#include <cuda_fp16.h>
#include <math.h>
#include <stdint.h>

#define BB 256
#define TT 512
#define HH 512
#define G4 2048
#define LSC 1024.0f

// ---- device images (static; no allocation anywhere) ----
__device__ uint4 g_ximg [(size_t)TT * 2 * 1024];     // [t][half] : 4 ki * 4KB = 16KB
__device__ uint4 g_W1img[(size_t)32 * 16384];        // [gt] : 64 ki * (2KB hi + 2KB lo)
__device__ uint4 g_W0img[(size_t)32 * 9216];         // [gt] : 36 ki * 4KB
__device__ uint4 g_h0img[(size_t)2 * 2 * 8192];      // [slot][half] : 32 ki * 4KB
__device__ uint4 g_h1img[(size_t)2 * 2 * 8192];
__device__ float g_b0[G4], g_b1[G4];
__device__ float g_h1last[BB * HH];
__device__ unsigned g_cnt[2];

__device__ __forceinline__ float sg(float x) { return __fdividef(1.0f, 1.0f + __expf(-x)); }
__device__ __forceinline__ float th(float x) { return 1.0f - __fdividef(2.0f, __expf(2.0f * x) + 1.0f); }

__device__ __forceinline__ unsigned fpk2(float a, float b) {
    __half2 h = __floats2half2_rn(a, b);
    return *reinterpret_cast<unsigned*>(&h);
}
__device__ __forceinline__ void wsplit2(float a, float b, unsigned& hi, unsigned& lo) {
    __half ha = __float2half_rn(a), hb = __float2half_rn(b);
    float ra = (a - __half2float(ha)) * LSC;
    float rb = (b - __half2float(hb)) * LSC;
    hi = (unsigned)__half_as_ushort(ha) | ((unsigned)__half_as_ushort(hb) << 16);
    lo = fpk2(ra, rb);
}

#define MMA(c, a, bx, by) \
    asm volatile("mma.sync.aligned.m16n8k16.row.col.f32.f16.f16.f32 " \
        "{%0,%1,%2,%3}, {%4,%5,%6,%7}, {%8,%9}, {%0,%1,%2,%3};" \
        : "+f"((c)[0]), "+f"((c)[1]), "+f"((c)[2]), "+f"((c)[3]) \
        : "r"((a).x), "r"((a).y), "r"((a).z), "r"((a).w), "r"(bx), "r"(by))

// =================== pack: build fragment-exact images (unchanged, proven) ===================
__global__ void pack_kernel(const float* __restrict__ x,
    const float* __restrict__ wi0, const float* __restrict__ wh0,
    const float* __restrict__ bi0, const float* __restrict__ bh0,
    const float* __restrict__ wi1, const float* __restrict__ wh1,
    const float* __restrict__ bi1, const float* __restrict__ bh1)
{
    const long long stride = (long long)gridDim.x * blockDim.x;
    const long long t0 = (long long)blockIdx.x * blockDim.x + threadIdx.x;
    if (t0 == 0) { g_cnt[0] = 0u; g_cnt[1] = 0u; }
    for (long long i = t0; i < G4; i += stride) { g_b0[i] = bi0[i] + bh0[i]; g_b1[i] = bi1[i] + bh1[i]; }
    uint4 z = make_uint4(0, 0, 0, 0);
    for (long long i = t0; i < 2 * 2 * 8192; i += stride) { g_h0img[i] = z; g_h1img[i] = z; }

    // ---- x image (fp16 single plane)
    for (long long i = t0; i < (long long)TT * 2 * 4 * 8 * 32; i += stride) {
        int lane = (int)(i & 31), mi = (int)((i >> 5) & 7), ki = (int)((i >> 8) & 3);
        int half = (int)((i >> 10) & 1), t = (int)(i >> 11);
        int r0 = mi * 16 + (lane >> 2), k0 = ki * 16 + (lane & 3) * 2;
        const float* xb = x + ((size_t)(half * 128 + r0) * TT + t) * 64;
        const float* xb8 = xb + (size_t)8 * TT * 64;
        uint4 hi;
        hi.x = fpk2(xb [k0],     xb [k0 + 1]);
        hi.y = fpk2(xb8[k0],     xb8[k0 + 1]);
        hi.z = fpk2(xb [k0 + 8], xb [k0 + 9]);
        hi.w = fpk2(xb8[k0 + 8], xb8[k0 + 9]);
        char* dst = (char*)g_ximg + ((size_t)t * 2 + half) * 16384 + ki * 4096 + (mi * 32 + lane) * 16;
        *(uint4*)dst = hi;
    }

    // ---- W1 image
    for (long long i = t0; i < (long long)32 * 64 * 32 * 4; i += stride) {
        int p = (int)(i & 3), lane = (int)((i >> 2) & 31), ki = (int)((i >> 7) & 63), gt = (int)(i >> 13);
        int j0 = p * 16 + (lane >> 2), j1 = j0 + 8;
        int k0 = ki * 16 + (lane & 3) * 2;
        int G0 = (j0 & 3) * 512 + gt * 16 + (j0 >> 2);
        int G1 = (j1 & 3) * 512 + gt * 16 + (j1 >> 2);
        const float* s00 = (k0 < 512)     ? wi1 + (size_t)G0 * 512 + k0     : wh1 + (size_t)G0 * 512 + k0 - 512;
        const float* s08 = (k0 + 8 < 512) ? wi1 + (size_t)G0 * 512 + k0 + 8 : wh1 + (size_t)G0 * 512 + k0 + 8 - 512;
        const float* s10 = (k0 < 512)     ? wi1 + (size_t)G1 * 512 + k0     : wh1 + (size_t)G1 * 512 + k0 - 512;
        const float* s18 = (k0 + 8 < 512) ? wi1 + (size_t)G1 * 512 + k0 + 8 : wh1 + (size_t)G1 * 512 + k0 + 8 - 512;
        uint4 hi, lo;
        wsplit2(s00[0], s00[1], hi.x, lo.x);
        wsplit2(s08[0], s08[1], hi.y, lo.y);
        wsplit2(s10[0], s10[1], hi.z, lo.z);
        wsplit2(s18[0], s18[1], hi.w, lo.w);
        char* dst = (char*)g_W1img + (size_t)gt * 262144 + ki * 4096 + (p * 32 + lane) * 16;
        *(uint4*)dst = hi; *(uint4*)(dst + 2048) = lo;
    }

    // ---- W0 image: K = 576 -> 36 ki
    for (long long i = t0; i < (long long)32 * 36 * 32 * 4; i += stride) {
        int p = (int)(i & 3), lane = (int)((i >> 2) & 31);
        int rem = (int)(i >> 7); int ki = rem % 36, gt = rem / 36;
        int j0 = p * 16 + (lane >> 2), j1 = j0 + 8;
        int k0 = ki * 16 + (lane & 3) * 2;
        int G0 = (j0 & 3) * 512 + gt * 16 + (j0 >> 2);
        int G1 = (j1 & 3) * 512 + gt * 16 + (j1 >> 2);
        const float* s00 = (k0 < 64)     ? wi0 + (size_t)G0 * 64 + k0     : wh0 + (size_t)G0 * 512 + k0 - 64;
        const float* s08 = (k0 + 8 < 64) ? wi0 + (size_t)G0 * 64 + k0 + 8 : wh0 + (size_t)G0 * 512 + k0 + 8 - 64;
        const float* s10 = (k0 < 64)     ? wi0 + (size_t)G1 * 64 + k0     : wh0 + (size_t)G1 * 512 + k0 - 64;
        const float* s18 = (k0 + 8 < 64) ? wi0 + (size_t)G1 * 64 + k0 + 8 : wh0 + (size_t)G1 * 512 + k0 + 8 - 64;
        uint4 hi, lo;
        wsplit2(s00[0], s00[1], hi.x, lo.x);
        wsplit2(s08[0], s08[1], hi.y, lo.y);
        wsplit2(s10[0], s10[1], hi.z, lo.z);
        wsplit2(s18[0], s18[1], hi.w, lo.w);
        char* dst = (char*)g_W0img + (size_t)gt * 147456 + ki * 4096 + (p * 32 + lane) * 16;
        *(uint4*)dst = hi; *(uint4*)(dst + 2048) = lo;
    }
}

// =================== grid barrier (cumulative, 2 domains of 64 CTAs) ===================
__device__ __forceinline__ void gbar(int dom, unsigned& tgt)
{
    __syncthreads();
    if (threadIdx.x == 0) {
        __threadfence();
        tgt += 64;
        atomicAdd(&g_cnt[dom], 1u);
        while (*(volatile unsigned*)&g_cnt[dom] < tgt) { }
        __threadfence();
    }
    __syncthreads();
}

// =================== one layer-step: W from SMEM, 4-stage A prefetch ===================
__device__ void stepH(const char* __restrict__ aA, int nA,
                      const char* __restrict__ aB, int nB,
                      const uint4* __restrict__ wS,      // SMEM W (hi planes, 128 uint4/chunk)
                      const float* __restrict__ bs, float* creg,
                      char* hImg, float* hlastBase, int gt, float (*Ds)[68])
{
    const int tid = threadIdx.x, lane = tid & 31;
    const int wz = (tid >> 5) & 3;       // row slice 0..3
    const int wg = tid >> 7;             // col half 0..1
    const int nCh = nA + nB;             // 36 or 64 : divisible by 4
    float acc[2][4][4];
    #pragma unroll
    for (int m = 0; m < 2; m++)
        #pragma unroll
        for (int n = 0; n < 4; n++)
            #pragma unroll
            for (int q = 0; q < 4; q++) acc[m][n][q] = 0.f;

    uint4 ahA[2], ahB[2], ahC[2], ahD[2];
    uint4 whA[2], whB[2];
    const int wb0 = (wg * 2) * 32 + lane, wb1 = (wg * 2 + 1) * 32 + lane;

#define LDA(S, c) do { \
    const char* ab_ = ((c) < nA) ? aA + (size_t)(c) * 4096 : aB + (size_t)((c) - nA) * 4096; \
    const char* pa_ = ab_ + ((wz * 2) * 32 + lane) * 16; \
    ah##S[0] = *(const uint4*)pa_; \
    ah##S[1] = *(const uint4*)(pa_ + 512); \
} while (0)

#define LDW(S, c) do { \
    wh##S[0] = wS[(c) * 128 + wb0]; \
    wh##S[1] = wS[(c) * 128 + wb1]; \
} while (0)

#define MMAC(S, T) do { \
    _Pragma("unroll") \
    for (int m_ = 0; m_ < 2; m_++) \
        _Pragma("unroll") \
        for (int p_ = 0; p_ < 2; p_++) { \
            MMA(acc[m_][2*p_],   ah##S[m_], wh##T[p_].x, wh##T[p_].y); \
            MMA(acc[m_][2*p_+1], ah##S[m_], wh##T[p_].z, wh##T[p_].w); \
        } \
} while (0)

    LDA(A, 0); LDA(B, 1); LDA(C, 2);
    LDW(A, 0);
    for (int c = 0; c < nCh; c += 4) {
        LDA(D, c + 3);                LDW(B, c + 1);                 MMAC(A, A);
        if (c + 4 < nCh) LDA(A, c + 4); LDW(A, c + 2);               MMAC(B, B);
        if (c + 5 < nCh) LDA(B, c + 5); LDW(B, c + 3);               MMAC(C, A);
        if (c + 6 < nCh) LDA(C, c + 6); if (c + 4 < nCh) LDW(A, c + 4); MMAC(D, B);
    }
#undef LDA
#undef LDW
#undef MMAC

    // ---- stage D to SMEM (row-major) ----
    #pragma unroll
    for (int m = 0; m < 2; m++)
        #pragma unroll
        for (int n = 0; n < 4; n++) {
            int r0 = wz * 32 + m * 16 + (lane >> 2);
            int c0 = (wg * 4 + n) * 8 + (lane & 3) * 2;
            Ds[r0][c0]     = acc[m][n][0];
            Ds[r0][c0 + 1] = acc[m][n][1];
            Ds[r0 + 8][c0]     = acc[m][n][2];
            Ds[r0 + 8][c0 + 1] = acc[m][n][3];
        }
    __syncthreads();

    // ---- gate math: thread owns row tid>>1, unit-half tid&1 (8 units) ----
    const int r  = tid >> 1;
    const int uh = tid & 1;
    float h[8];
    #pragma unroll
    for (int i = 0; i < 8; i++) {
        int ul = uh * 8 + i;
        float gi = sg(Ds[r][4*ul + 0] + bs[4*ul + 0]);
        float gf = sg(Ds[r][4*ul + 1] + bs[4*ul + 1]);
        float gg = th(Ds[r][4*ul + 2] + bs[4*ul + 2]);
        float go = sg(Ds[r][4*ul + 3] + bs[4*ul + 3]);
        float cc = gf * creg[i] + gi * gg;
        creg[i] = cc;
        h[i] = go * th(cc);
    }

    if (hImg) {   // write h as fp16 A-fragments at ki = gt (single plane)
        int rl = r & 15, mi = r >> 4;
        char* base = hImg + gt * 4096 + mi * 512;
        #pragma unroll
        for (int j = 0; j < 4; j++) {
            unsigned hi32 = fpk2(h[2*j], h[2*j + 1]);
            int lane2 = (rl & 7) * 4 + j;
            int p4 = (rl >> 3) + 2 * uh;
            *(unsigned*)(base + lane2 * 16 + p4 * 4) = hi32;
        }
    }
    if (hlastBase) {
        float* dst = hlastBase + (size_t)r * HH + gt * 16 + uh * 8;
        #pragma unroll
        for (int i = 0; i < 8; i++) dst[i] = h[i];
    }
    __syncthreads();
}

// =================== persistent recurrence ===================
__global__ __launch_bounds__(256, 1) void lstm_persistent()
{
    extern __shared__ uint4 wS[];          // staged W hi-planes (<=128KB)
    __shared__ float Ds[128][68];
    __shared__ float bs[64];
    const int tid = threadIdx.x, cta = blockIdx.x;
    const int lyr  = cta >> 6;          // 0: layer1 worker, 1: layer0 worker
    const int half = (cta >> 5) & 1;
    const int gt   = cta & 31;

    // ---- stage this CTA's W (hi plane only) into SMEM once ----
    const uint4* wsrc = lyr ? (g_W0img + (size_t)gt * 9216) : (g_W1img + (size_t)gt * 16384);
    const int nWc = lyr ? 36 : 64;
    for (int j = tid; j < nWc * 128; j += 256)
        wS[j] = wsrc[(size_t)(j >> 7) * 256 + (j & 127)];

    const float* bias = lyr ? g_b0 : g_b1;
    if (tid < 64) bs[tid] = bias[(tid & 3) * 512 + gt * 16 + (tid >> 2)];
    __syncthreads();

    float creg[8];
    #pragma unroll
    for (int i = 0; i < 8; i++) creg[i] = 0.f;
    unsigned tgt = 0u;

    #define XI(t)  ((char*)g_ximg  + ((size_t)(t) * 2 + half) * 16384)
    #define H0I(s) ((char*)g_h0img + ((size_t)((s) * 2 + half)) * 131072)
    #define H1I(s) ((char*)g_h1img + ((size_t)((s) * 2 + half)) * 131072)

    // prologue: layer0(t=0) reads h0 slot1 (zeros), writes slot0
    if (lyr == 1)
        stepH(XI(0), 4, H0I(1), 32, wS, bs, creg, H0I(0), nullptr, gt, Ds);
    gbar(half, tgt);

    for (int p = 0; p < TT - 1; p++) {
        const int s = p & 1;
        if (lyr == 0)   // layer1(p): A = h0(slot s) || h1(slot s^1); writes h1 slot s
            stepH(H0I(s), 32, H1I(s ^ 1), 32, wS, bs, creg, H1I(s), nullptr, gt, Ds);
        else            // layer0(p+1): A = x(p+1) || h0(slot s); writes h0 slot s^1
            stepH(XI(p + 1), 4, H0I(s), 32, wS, bs, creg, H0I(s ^ 1), nullptr, gt, Ds);
        gbar(half, tgt);
    }

    // layer1(511): A = h0 slot1 || h1 slot0 ; fp32 output only
    if (lyr == 0)
        stepH(H0I(1), 32, H1I(0), 32, wS, bs, creg, nullptr,
              g_h1last + (size_t)half * 128 * HH, gt, Ds);
}

// =================== final FC ===================
__global__ void fc_kernel(const float* __restrict__ fc_w, const float* __restrict__ fc_b,
                          float* __restrict__ out)
{
    const int b = blockIdx.x;
    const float* h = g_h1last + (size_t)b * HH;
    float s = 0.f;
    for (int k = threadIdx.x; k < HH; k += 128) s += h[k] * fc_w[k];
    #pragma unroll
    for (int off = 16; off > 0; off >>= 1) s += __shfl_xor_sync(0xffffffffu, s, off);
    __shared__ float ws[4];
    if ((threadIdx.x & 31) == 0) ws[threadIdx.x >> 5] = s;
    __syncthreads();
    if (threadIdx.x == 0) out[b] = ws[0] + ws[1] + ws[2] + ws[3] + fc_b[0];
}

extern "C" void kernel_launch(void* const* d_in, const int* in_sizes, int n_in,
                              void* d_out, int out_size)
{
    const float* x   = (const float*)d_in[0];
    const float* wi0 = (const float*)d_in[1];
    const float* wh0 = (const float*)d_in[2];
    const float* bi0 = (const float*)d_in[3];
    const float* bh0 = (const float*)d_in[4];
    const float* wi1 = (const float*)d_in[5];
    const float* wh1 = (const float*)d_in[6];
    const float* bi1 = (const float*)d_in[7];
    const float* bh1 = (const float*)d_in[8];
    const float* fcw = (const float*)d_in[9];
    const float* fcb = (const float*)d_in[10];
    float* out = (float*)d_out;

    static int smem_set = 0;
    if (!smem_set) {
        cudaFuncSetAttribute(lstm_persistent,
                             cudaFuncAttributeMaxDynamicSharedMemorySize, 131072);
        smem_set = 1;
    }

    pack_kernel<<<1024, 256>>>(x, wi0, wh0, bi0, bh0, wi1, wh1, bi1, bh1);
    lstm_persistent<<<128, 256, 131072>>>();
    fc_kernel<<<BB, 128>>>(fcw, fcb, out);
}